// round 2
// baseline (speedup 1.0000x reference)
#include <cuda_runtime.h>
#include <cuda_bf16.h>
#include <cstdint>

#define T_STEPS 1024
#define H_DIM   768
#define B_DIM   32
#define G_DIM   (3*H_DIM)     // 2304

// ---------------- static device scratch (no allocations allowed) ----------------
__device__ float g_xg[(size_t)T_STEPS * G_DIM * B_DIM];     // [t][g][b]  288MB
__device__ float g_actA[(size_t)T_STEPS * H_DIM * B_DIM];   // [t][d][b]   96MB
__device__ float g_actB[(size_t)T_STEPS * H_DIM * B_DIM];   // [t][d][b]   96MB
__device__ float g_h[2][H_DIM * B_DIM];                      // ping-pong h, [j][b]
__device__ unsigned int g_arrive = 0;
__device__ volatile unsigned int g_gen = 0;

// ---------------- software grid barrier (all CTAs co-resident) ----------------
__device__ __forceinline__ void grid_barrier() {
    __syncthreads();
    if (threadIdx.x == 0) {
        unsigned int target = gridDim.x;
        __threadfence();
        unsigned int gen = g_gen;                  // read BEFORE arriving
        if (atomicAdd(&g_arrive, 1) == target - 1) {
            atomicExch(&g_arrive, 0);
            __threadfence();
            g_gen = gen + 1;                       // release
        } else {
            while (g_gen == gen) { }
            __threadfence();
        }
    }
    __syncthreads();
}

// ---------------- transpose x[b][t][d] -> actA[t][d][b] ----------------
__global__ void __launch_bounds__(256) transpose_x(const float* __restrict__ x,
                                                   float* __restrict__ out) {
    __shared__ float sm[64][33];
    int t = blockIdx.x;
    int d0 = blockIdx.y * 64;
#pragma unroll
    for (int i = 0; i < 8; ++i) {
        int lin = i * 256 + threadIdx.x;
        int b = lin >> 6, dl = lin & 63;
        sm[dl][b] = x[((size_t)b * T_STEPS + t) * H_DIM + d0 + dl];
    }
    __syncthreads();
#pragma unroll
    for (int i = 0; i < 8; ++i) {
        int lin = i * 256 + threadIdx.x;
        int dl = lin >> 5, b = lin & 31;
        out[((size_t)t * H_DIM + d0 + dl) * B_DIM + b] = sm[dl][b];
    }
}

// ---------------- input-projection GEMM ----------------
// C[g][m] = sum_d W[g][d] * act[tsrc(m)][d][b(m)] + bias[g],  m = t*32+b
// written to xg[t][g][b]
#define BM 128
#define BN 128
#define BK 8
__global__ void __launch_bounds__(256) gemm_xg(
    const float* __restrict__ W,     // [2304][768]
    const float* __restrict__ bias,  // [2304]
    const float* __restrict__ act,   // [1024][768][32]
    float* __restrict__ xg,          // [1024][2304][32]
    int rev)
{
    __shared__ float As[BK][BM];
    __shared__ float Bs[BK][BN];
    float acc[8][8];
#pragma unroll
    for (int i = 0; i < 8; ++i)
#pragma unroll
        for (int j = 0; j < 8; ++j) acc[i][j] = 0.f;

    int tid = threadIdx.x;
    int tx = tid & 15, ty = tid >> 4;
    int gBase = blockIdx.y * BM;
    int mBase = blockIdx.x * BN;

    int aRow = tid >> 1, aCol = (tid & 1) * 4;
    int bRow = tid >> 5, bCol = (tid & 31) * 4;
    int mB = mBase + bCol;
    int tIdx = mB >> 5, bIdx = mB & 31;
    int tsrc = rev ? (T_STEPS - 1 - tIdx) : tIdx;
    size_t bAddrBase = (size_t)tsrc * H_DIM * B_DIM + bIdx;

    const size_t aRowOff = (size_t)(gBase + aRow) * H_DIM;

    for (int k0 = 0; k0 < H_DIM; k0 += BK) {
        float4 av = *(const float4*)&W[aRowOff + k0 + aCol];
        float4 bv = *(const float4*)&act[bAddrBase + (size_t)(k0 + bRow) * B_DIM];
        As[aCol + 0][aRow] = av.x;
        As[aCol + 1][aRow] = av.y;
        As[aCol + 2][aRow] = av.z;
        As[aCol + 3][aRow] = av.w;
        *(float4*)&Bs[bRow][bCol] = bv;
        __syncthreads();
#pragma unroll
        for (int kk = 0; kk < BK; ++kk) {
            float ra[8], rb[8];
#pragma unroll
            for (int i = 0; i < 8; ++i) ra[i] = As[kk][ty * 8 + i];
#pragma unroll
            for (int j = 0; j < 8; ++j) rb[j] = Bs[kk][tx * 8 + j];
#pragma unroll
            for (int i = 0; i < 8; ++i)
#pragma unroll
                for (int j = 0; j < 8; ++j)
                    acc[i][j] = fmaf(ra[i], rb[j], acc[i][j]);
        }
        __syncthreads();
    }
    // epilogue: xg[t][g][b]
    int m0 = mBase + tx * 8;
    int tI = m0 >> 5, bI = m0 & 31;   // 8 consecutive m share t
#pragma unroll
    for (int i = 0; i < 8; ++i) {
        int g = gBase + ty * 8 + i;
        float bv = bias[g];
        size_t o = (size_t)tI * (G_DIM * B_DIM) + (size_t)g * B_DIM + bI;
        float4 o0 = make_float4(acc[i][0] + bv, acc[i][1] + bv, acc[i][2] + bv, acc[i][3] + bv);
        float4 o1 = make_float4(acc[i][4] + bv, acc[i][5] + bv, acc[i][6] + bv, acc[i][7] + bv);
        *(float4*)&xg[o]     = o0;
        *(float4*)&xg[o + 4] = o1;
    }
}

// ---------------- persistent recurrent kernel ----------------
// 128 CTAs x 384 threads. CTA owns 6 hidden units (j), 12 warps = 3 j-pairs x 4 k-quarters.
#define NCTAS   128
#define NTHREADS 384
#define JPC     6
#define KQL     (H_DIM / 4)   // 192
#define SMEM_REC ((JPC*3*H_DIM + H_DIM*B_DIM + JPC*3*4*B_DIM + 32) * sizeof(float))

__global__ void __launch_bounds__(NTHREADS, 1) gru_recurrent(
    const float* __restrict__ Whh,   // [2304][768]
    const float* __restrict__ bhh,   // [2304]
    const float* __restrict__ xg,    // [t][g][b]
    const float* __restrict__ res,   // prev act [t][d][b] or null
    float* __restrict__ out,
    int out_mode)                    // 0: act layout [t][j][b]; 1: d_out [b][T-1-t][j]
{
    extern __shared__ float sm[];
    float* Ws  = sm;                                  // [jl][g][k] : 6*3*768
    float* h_s = Ws + JPC * 3 * H_DIM;                // [k][b]     : 768*32
    float* part = h_s + H_DIM * B_DIM;                // [jl][g][kq][b] : 6*3*4*32
    float* bsh = part + JPC * 3 * 4 * B_DIM;          // 18

    const int tid = threadIdx.x;
    const int cta = blockIdx.x;
    const int lane = tid & 31;
    const int w = tid >> 5;          // 0..11
    const int jp = w >> 2;           // 0..2
    const int kq = w & 3;            // 0..3
    const int j0 = jp * 2, j1 = jp * 2 + 1;

    // load W_hh slice: rows (g*768 + cta*6 + jl)
    for (int i = tid; i < JPC * 3 * H_DIM / 4; i += NTHREADS) {
        int f = i * 4;
        int jl = f / (3 * H_DIM);
        int rem = f - jl * 3 * H_DIM;
        int g = rem / H_DIM;
        int k = rem - g * H_DIM;
        *(float4*)&Ws[f] =
            *(const float4*)&Whh[(size_t)(g * H_DIM + cta * JPC + jl) * H_DIM + k];
    }
    if (tid < JPC * 3) {
        int jl = tid / 3, g = tid % 3;
        bsh[tid] = bhh[g * H_DIM + cta * JPC + jl];
    }
    // zero own slice of h[0]
    if (tid < JPC * B_DIM) {
        int jl = tid >> 5;
        g_h[0][(cta * JPC + jl) * B_DIM + lane] = 0.f;
    }
    __threadfence();
    grid_barrier();

    const float* w0 = &Ws[(j0 * 3 + 0) * H_DIM];
    const float* w1 = &Ws[(j0 * 3 + 1) * H_DIM];
    const float* w2 = &Ws[(j0 * 3 + 2) * H_DIM];
    const float* w3 = &Ws[(j1 * 3 + 0) * H_DIM];
    const float* w4 = &Ws[(j1 * 3 + 1) * H_DIM];
    const float* w5 = &Ws[(j1 * 3 + 2) * H_DIM];
    const int kbase = kq * KQL;
    const int jlf = tid >> 5;              // finalize j (tid<192)
    const int jgf = cta * JPC + jlf;

    for (int t = 0; t < T_STEPS; ++t) {
        const float* hcur = g_h[t & 1];
        float* hnext = g_h[(t & 1) ^ 1];

        // prefetch xg + residual for finalize threads (independent of h)
        float xr = 0.f, xz = 0.f, xn = 0.f, rv = 0.f;
        if (tid < JPC * B_DIM) {
            size_t base = (size_t)t * (G_DIM * B_DIM);
            xr = xg[base + (size_t)(0 * H_DIM + jgf) * B_DIM + lane];
            xz = xg[base + (size_t)(1 * H_DIM + jgf) * B_DIM + lane];
            xn = xg[base + (size_t)(2 * H_DIM + jgf) * B_DIM + lane];
            if (res)
                rv = res[(size_t)(T_STEPS - 1 - t) * (H_DIM * B_DIM) +
                         (size_t)jgf * B_DIM + lane];
        }

        // stage full h into SMEM (24576 floats = 6144 float4 = 16/thread)
#pragma unroll
        for (int i = 0; i < 16; ++i) {
            int idx = (i * NTHREADS + tid) * 4;
            *(float4*)&h_s[idx] = *(const float4*)&hcur[idx];
        }
        __syncthreads();

        // k-quarter dot products for the j-pair (6 accumulators)
        float a0 = 0.f, a1 = 0.f, a2 = 0.f, a3 = 0.f, a4 = 0.f, a5 = 0.f;
        const float* hp = &h_s[kbase * B_DIM + lane];
#pragma unroll 4
        for (int k = 0; k < KQL; k += 4) {
            float h0 = hp[(k + 0) * B_DIM];
            float h1 = hp[(k + 1) * B_DIM];
            float h2 = hp[(k + 2) * B_DIM];
            float h3 = hp[(k + 3) * B_DIM];
            float4 v0 = *(const float4*)(w0 + kbase + k);
            float4 v1 = *(const float4*)(w1 + kbase + k);
            float4 v2 = *(const float4*)(w2 + kbase + k);
            float4 v3 = *(const float4*)(w3 + kbase + k);
            float4 v4 = *(const float4*)(w4 + kbase + k);
            float4 v5 = *(const float4*)(w5 + kbase + k);
            a0 = fmaf(h0, v0.x, a0); a0 = fmaf(h1, v0.y, a0); a0 = fmaf(h2, v0.z, a0); a0 = fmaf(h3, v0.w, a0);
            a1 = fmaf(h0, v1.x, a1); a1 = fmaf(h1, v1.y, a1); a1 = fmaf(h2, v1.z, a1); a1 = fmaf(h3, v1.w, a1);
            a2 = fmaf(h0, v2.x, a2); a2 = fmaf(h1, v2.y, a2); a2 = fmaf(h2, v2.z, a2); a2 = fmaf(h3, v2.w, a2);
            a3 = fmaf(h0, v3.x, a3); a3 = fmaf(h1, v3.y, a3); a3 = fmaf(h2, v3.z, a3); a3 = fmaf(h3, v3.w, a3);
            a4 = fmaf(h0, v4.x, a4); a4 = fmaf(h1, v4.y, a4); a4 = fmaf(h2, v4.z, a4); a4 = fmaf(h3, v4.w, a4);
            a5 = fmaf(h0, v5.x, a5); a5 = fmaf(h1, v5.y, a5); a5 = fmaf(h2, v5.z, a5); a5 = fmaf(h3, v5.w, a5);
        }
        part[((j0 * 3 + 0) * 4 + kq) * B_DIM + lane] = a0;
        part[((j0 * 3 + 1) * 4 + kq) * B_DIM + lane] = a1;
        part[((j0 * 3 + 2) * 4 + kq) * B_DIM + lane] = a2;
        part[((j1 * 3 + 0) * 4 + kq) * B_DIM + lane] = a3;
        part[((j1 * 3 + 1) * 4 + kq) * B_DIM + lane] = a4;
        part[((j1 * 3 + 2) * 4 + kq) * B_DIM + lane] = a5;
        __syncthreads();

        // finalize: 192 threads = 6 j x 32 b
        if (tid < JPC * B_DIM) {
            const float* p = &part[(jlf * 3) * 4 * B_DIM + lane];
            float hr = p[0 * B_DIM] + p[1 * B_DIM] + p[2 * B_DIM] + p[3 * B_DIM];
            float hz = p[4 * B_DIM] + p[5 * B_DIM] + p[6 * B_DIM] + p[7 * B_DIM];
            float hn = p[8 * B_DIM] + p[9 * B_DIM] + p[10 * B_DIM] + p[11 * B_DIM];
            hr += bsh[jlf * 3 + 0];
            hz += bsh[jlf * 3 + 1];
            hn += bsh[jlf * 3 + 2];
            float r = 1.f / (1.f + expf(-(xr + hr)));
            float z = 1.f / (1.f + expf(-(xz + hz)));
            float n = tanhf(xn + r * hn);
            float hprev = h_s[jgf * B_DIM + lane];
            float hv = (1.f - z) * n + z * hprev;
            hnext[jgf * B_DIM + lane] = hv;
            float ov = rv + hv;
            if (out_mode == 0)
                out[(size_t)t * (H_DIM * B_DIM) + (size_t)jgf * B_DIM + lane] = ov;
            else
                out[((size_t)lane * T_STEPS + (T_STEPS - 1 - t)) * H_DIM + jgf] = ov;
        }
        __threadfence();
        grid_barrier();
    }
}

// ---------------- host launcher ----------------
extern "C" void kernel_launch(void* const* d_in, const int* in_sizes, int n_in,
                              void* d_out, int out_size) {
    const float* x    = (const float*)d_in[0];
    const float* Wih0 = (const float*)d_in[1];
    const float* Whh0 = (const float*)d_in[2];
    const float* bih0 = (const float*)d_in[3];
    const float* bhh0 = (const float*)d_in[4];
    const float* WihS = (const float*)d_in[5];
    const float* WhhS = (const float*)d_in[6];
    const float* bihS = (const float*)d_in[7];
    const float* bhhS = (const float*)d_in[8];
    float* out = (float*)d_out;

    float *xgP, *actA, *actB;
    cudaGetSymbolAddress((void**)&xgP, g_xg);
    cudaGetSymbolAddress((void**)&actA, g_actA);
    cudaGetSymbolAddress((void**)&actB, g_actB);
    cudaFuncSetAttribute(gru_recurrent, cudaFuncAttributeMaxDynamicSharedMemorySize,
                         (int)SMEM_REC);

    transpose_x<<<dim3(T_STEPS, H_DIM / 64), 256>>>(x, actA);

    for (int l = 0; l < 4; ++l) {
        const float* Wih = (l == 0) ? Wih0 : WihS + (size_t)(l - 1) * G_DIM * H_DIM;
        const float* bih = (l == 0) ? bih0 : bihS + (size_t)(l - 1) * G_DIM;
        const float* Whh = (l == 0) ? Whh0 : WhhS + (size_t)(l - 1) * G_DIM * H_DIM;
        const float* bhh = (l == 0) ? bhh0 : bhhS + (size_t)(l - 1) * G_DIM;

        const float* ain = (l & 1) ? actB : actA;       // l=0:A, 1:B, 2:A, 3:B
        float* aout = (l == 3) ? out : ((l & 1) ? actA : actB);
        int rev = (l == 0) ? 0 : 1;

        gemm_xg<<<dim3((T_STEPS * B_DIM) / BN, G_DIM / BM), 256>>>(Wih, bih, ain, xgP, rev);
        gru_recurrent<<<NCTAS, NTHREADS, SMEM_REC>>>(
            Whh, bhh, xgP, (l == 0) ? nullptr : ain, aout, (l == 3) ? 1 : 0);
    }
}

// round 3
// speedup vs baseline: 1.1524x; 1.1524x over previous
#include <cuda_runtime.h>
#include <cuda_bf16.h>
#include <cstdint>

#define T_STEPS 1024
#define H_DIM   768
#define B_DIM   32
#define G_DIM   (3*H_DIM)     // 2304
#define KBIG    2304          // 3 x 768 (split-K for bf16x2 precision scheme)
#define M_BIG   (T_STEPS*B_DIM) // 32768

// ---------------- static device scratch (no allocations allowed) ----------------
__device__ float g_xg[(size_t)T_STEPS * G_DIM * B_DIM];     // [t][g][b]
__device__ float g_actA[(size_t)T_STEPS * H_DIM * B_DIM];   // [t][d][b]
__device__ float g_actB[(size_t)T_STEPS * H_DIM * B_DIM];   // [t][d][b]
__device__ __nv_bfloat16 g_Abig[(size_t)M_BIG * KBIG];      // [m][k]  151MB
__device__ __nv_bfloat16 g_Wbig[(size_t)4 * G_DIM * KBIG];  // [l][g][k] 42.5MB
__device__ float g_h[2][H_DIM * B_DIM];                     // ping-pong h, [j][b]
__device__ unsigned int g_arrive = 0;
__device__ volatile unsigned int g_gen = 0;

// ---------------- software grid barrier (all CTAs co-resident) ----------------
__device__ __forceinline__ void grid_barrier() {
    __syncthreads();
    if (threadIdx.x == 0) {
        unsigned int target = gridDim.x;
        __threadfence();
        unsigned int gen = g_gen;
        if (atomicAdd(&g_arrive, 1) == target - 1) {
            atomicExch(&g_arrive, 0);
            __threadfence();
            g_gen = gen + 1;
        } else {
            while (g_gen == gen) { }
            __threadfence();
        }
    }
    __syncthreads();
}

// ---------------- bf16 two-term split helpers ----------------
__device__ __forceinline__ void split_bf16(float v, __nv_bfloat16& hi, __nv_bfloat16& lo) {
    hi = __float2bfloat16(v);
    lo = __float2bfloat16(v - __bfloat162float(hi));
}

// x[b][t][d] -> Abig rows m=t*32+b, no flip (layer 0)
__global__ void __launch_bounds__(256) split_x0(const float* __restrict__ x,
                                                __nv_bfloat16* __restrict__ Ab) {
    int t = blockIdx.x;
    for (int i = threadIdx.x; i < 32 * H_DIM; i += 256) {
        int b = i / H_DIM, d = i % H_DIM;
        float v = x[((size_t)b * T_STEPS + t) * H_DIM + d];
        __nv_bfloat16 hi, lo; split_bf16(v, hi, lo);
        size_t r = ((size_t)t * 32 + b) * KBIG;
        Ab[r + d] = hi;                 // A_hi
        Ab[r + 768 + d] = lo;           // A_lo
        Ab[r + 1536 + d] = hi;          // A_hi
    }
}

// act[t][d][b] -> Abig rows m=t*32+b with time flip (layers 1..3)
__global__ void __launch_bounds__(256) split_act(const float* __restrict__ act,
                                                 __nv_bfloat16* __restrict__ Ab) {
    __shared__ float sm[64][33];
    int t = blockIdx.x;
    int d0 = blockIdx.y * 64;
    int ts = T_STEPS - 1 - t;
    for (int i = threadIdx.x; i < 64 * 32; i += 256) {
        int dl = i >> 5, b = i & 31;
        sm[dl][b] = act[((size_t)ts * H_DIM + d0 + dl) * B_DIM + b];
    }
    __syncthreads();
    for (int i = threadIdx.x; i < 32 * 64; i += 256) {
        int b = i >> 6, dl = i & 63;
        float v = sm[dl][b];
        __nv_bfloat16 hi, lo; split_bf16(v, hi, lo);
        size_t r = ((size_t)t * 32 + b) * KBIG;
        Ab[r + d0 + dl] = hi;
        Ab[r + 768 + d0 + dl] = lo;
        Ab[r + 1536 + d0 + dl] = hi;
    }
}

// W[g][d] -> Wbig[g][k] = [W_hi | W_hi | W_lo]
__global__ void __launch_bounds__(256) split_w(const float* __restrict__ W,
                                               __nv_bfloat16* __restrict__ Wb) {
    int i = blockIdx.x * 256 + threadIdx.x;
    if (i >= G_DIM * H_DIM) return;
    int g = i / H_DIM, d = i % H_DIM;
    float v = W[i];
    __nv_bfloat16 hi, lo; split_bf16(v, hi, lo);
    size_t r = (size_t)g * KBIG;
    Wb[r + d] = hi;
    Wb[r + 768 + d] = hi;
    Wb[r + 1536 + d] = lo;
}

// ---------------- tensor-core GEMM: xg[t][g][b] = Abig @ Wbig^T + bias ----------------
#define GBK 32
#define SPITCH 40            // bf16 elems per smem row (80B, padded for conflict-free LDSM)
#define ASZ (128 * SPITCH)   // elems per A (or B) tile
#define STAGE_ELEMS (2 * ASZ)
#define NSTAGES 3
#define KTILES (KBIG / GBK)  // 72

__device__ __forceinline__ void cp16(void* s, const void* g) {
    uint32_t sa = (uint32_t)__cvta_generic_to_shared(s);
    asm volatile("cp.async.cg.shared.global [%0], [%1], 16;\n" :: "r"(sa), "l"(g));
}
__device__ __forceinline__ void ldsm_x4(uint32_t& r0, uint32_t& r1, uint32_t& r2, uint32_t& r3,
                                        const __nv_bfloat16* p) {
    uint32_t a = (uint32_t)__cvta_generic_to_shared(p);
    asm volatile("ldmatrix.sync.aligned.m8n8.x4.shared.b16 {%0,%1,%2,%3}, [%4];\n"
                 : "=r"(r0), "=r"(r1), "=r"(r2), "=r"(r3) : "r"(a));
}
__device__ __forceinline__ void mma_bf16(float* c, const uint32_t* a, const uint32_t* b) {
    asm volatile("mma.sync.aligned.m16n8k16.row.col.f32.bf16.bf16.f32 "
                 "{%0,%1,%2,%3}, {%4,%5,%6,%7}, {%8,%9}, {%0,%1,%2,%3};\n"
                 : "+f"(c[0]), "+f"(c[1]), "+f"(c[2]), "+f"(c[3])
                 : "r"(a[0]), "r"(a[1]), "r"(a[2]), "r"(a[3]), "r"(b[0]), "r"(b[1]));
}

// grid (18, 256): blockIdx.x -> gBase (N), blockIdx.y -> mBase (M). 256 threads, 8 warps (4M x 2N).
__global__ void __launch_bounds__(256) gemm_tc(
    const __nv_bfloat16* __restrict__ A,   // [32768][2304]
    const __nv_bfloat16* __restrict__ Wb,  // [2304][2304]
    const float* __restrict__ bias,        // [2304]
    float* __restrict__ xg)                // [t][g][b]
{
    extern __shared__ char smem_raw[];
    __nv_bfloat16* sm = (__nv_bfloat16*)smem_raw;

    const int tid = threadIdx.x;
    const int lane = tid & 31;
    const int warp = tid >> 5;
    const int wm = warp >> 1;          // 0..3
    const int wn = warp & 1;           // 0..1
    const int gBase = blockIdx.x * 128;
    const int mBase = blockIdx.y * 128;

    float acc[2][8][4];
#pragma unroll
    for (int i = 0; i < 2; ++i)
#pragma unroll
        for (int j = 0; j < 8; ++j)
#pragma unroll
            for (int k = 0; k < 4; ++k) acc[i][j][k] = 0.f;

    // tile loader: 512 16B-chunks per matrix tile (128 rows x 4 chunks), 2 per thread
    auto load_tile = [&](int stage, int kt) {
        __nv_bfloat16* As = sm + stage * STAGE_ELEMS;
        __nv_bfloat16* Bs = As + ASZ;
        int k0 = kt * GBK;
#pragma unroll
        for (int i = 0; i < 2; ++i) {
            int task = i * 256 + tid;
            int row = task >> 2, ch = task & 3;
            cp16(As + row * SPITCH + ch * 8,
                 A + (size_t)(mBase + row) * KBIG + k0 + ch * 8);
            cp16(Bs + row * SPITCH + ch * 8,
                 Wb + (size_t)(gBase + row) * KBIG + k0 + ch * 8);
        }
    };

    // prologue: fill 3 stages
#pragma unroll
    for (int s = 0; s < NSTAGES; ++s) {
        load_tile(s, s);
        asm volatile("cp.async.commit_group;\n" ::: "memory");
    }

    for (int kt = 0; kt < KTILES; ++kt) {
        asm volatile("cp.async.wait_group %0;\n" :: "n"(NSTAGES - 1) : "memory");
        __syncthreads();
        int s = kt % NSTAGES;
        const __nv_bfloat16* As = sm + s * STAGE_ELEMS;
        const __nv_bfloat16* Bs = As + ASZ;

#pragma unroll
        for (int kk = 0; kk < 2; ++kk) {
            uint32_t af[2][4];
            uint32_t bf[8][2];
#pragma unroll
            for (int mt = 0; mt < 2; ++mt) {
                const __nv_bfloat16* p = As + (wm * 32 + mt * 16 + (lane & 15)) * SPITCH
                                            + kk * 16 + (lane >> 4) * 8;
                ldsm_x4(af[mt][0], af[mt][1], af[mt][2], af[mt][3], p);
            }
#pragma unroll
            for (int np = 0; np < 4; ++np) {
                int grp = lane >> 3;
                const __nv_bfloat16* p = Bs + (wn * 64 + np * 16 + (grp >> 1) * 8 + (lane & 7)) * SPITCH
                                            + kk * 16 + (grp & 1) * 8;
                uint32_t r0, r1, r2, r3;
                ldsm_x4(r0, r1, r2, r3, p);
                bf[2 * np][0] = r0; bf[2 * np][1] = r1;
                bf[2 * np + 1][0] = r2; bf[2 * np + 1][1] = r3;
            }
#pragma unroll
            for (int mt = 0; mt < 2; ++mt)
#pragma unroll
                for (int nt = 0; nt < 8; ++nt)
                    mma_bf16(acc[mt][nt], af[mt], bf[nt]);
        }
        __syncthreads();
        int ktn = kt + NSTAGES;
        if (ktn < KTILES) load_tile(ktn % NSTAGES, ktn);
        asm volatile("cp.async.commit_group;\n" ::: "memory");
    }
    asm volatile("cp.async.wait_all;\n" ::: "memory");
    __syncthreads();

    // epilogue: warp m-tile (32 rows) == one t; stage [64 g][32 b] in smem, write coalesced
    float* ebuf = (float*)smem_raw + warp * (64 * 33);
#pragma unroll
    for (int mt = 0; mt < 2; ++mt)
#pragma unroll
        for (int nt = 0; nt < 8; ++nt) {
            int b0 = mt * 16 + (lane >> 2);
            int gl = nt * 8 + (lane & 3) * 2;
            ebuf[gl * 33 + b0]            = acc[mt][nt][0];
            ebuf[(gl + 1) * 33 + b0]      = acc[mt][nt][1];
            ebuf[gl * 33 + b0 + 8]        = acc[mt][nt][2];
            ebuf[(gl + 1) * 33 + b0 + 8]  = acc[mt][nt][3];
        }
    __syncwarp();
    int t = blockIdx.y * 4 + wm;
    int g0 = gBase + wn * 64;
    size_t obase = (size_t)t * (G_DIM * B_DIM);
#pragma unroll 4
    for (int g = 0; g < 64; ++g) {
        xg[obase + (size_t)(g0 + g) * B_DIM + lane] = ebuf[g * 33 + lane] + bias[g0 + g];
    }
}

// ---------------- persistent recurrent kernel (unchanged from R2) ----------------
#define NCTAS   128
#define NTHREADS 384
#define JPC     6
#define KQL     (H_DIM / 4)
#define SMEM_REC ((JPC*3*H_DIM + H_DIM*B_DIM + JPC*3*4*B_DIM + 32) * sizeof(float))

__global__ void __launch_bounds__(NTHREADS, 1) gru_recurrent(
    const float* __restrict__ Whh,
    const float* __restrict__ bhh,
    const float* __restrict__ xg,
    const float* __restrict__ res,
    float* __restrict__ out,
    int out_mode)
{
    extern __shared__ float smf[];
    float* Ws  = smf;
    float* h_s = Ws + JPC * 3 * H_DIM;
    float* part = h_s + H_DIM * B_DIM;
    float* bsh = part + JPC * 3 * 4 * B_DIM;

    const int tid = threadIdx.x;
    const int cta = blockIdx.x;
    const int lane = tid & 31;
    const int w = tid >> 5;
    const int jp = w >> 2;
    const int kq = w & 3;
    const int j0 = jp * 2, j1 = jp * 2 + 1;

    for (int i = tid; i < JPC * 3 * H_DIM / 4; i += NTHREADS) {
        int f = i * 4;
        int jl = f / (3 * H_DIM);
        int rem = f - jl * 3 * H_DIM;
        int g = rem / H_DIM;
        int k = rem - g * H_DIM;
        *(float4*)&Ws[f] =
            *(const float4*)&Whh[(size_t)(g * H_DIM + cta * JPC + jl) * H_DIM + k];
    }
    if (tid < JPC * 3) {
        int jl = tid / 3, g = tid % 3;
        bsh[tid] = bhh[g * H_DIM + cta * JPC + jl];
    }
    if (tid < JPC * B_DIM) {
        int jl = tid >> 5;
        g_h[0][(cta * JPC + jl) * B_DIM + lane] = 0.f;
    }
    __threadfence();
    grid_barrier();

    const float* w0 = &Ws[(j0 * 3 + 0) * H_DIM];
    const float* w1 = &Ws[(j0 * 3 + 1) * H_DIM];
    const float* w2 = &Ws[(j0 * 3 + 2) * H_DIM];
    const float* w3 = &Ws[(j1 * 3 + 0) * H_DIM];
    const float* w4 = &Ws[(j1 * 3 + 1) * H_DIM];
    const float* w5 = &Ws[(j1 * 3 + 2) * H_DIM];
    const int kbase = kq * KQL;
    const int jlf = tid >> 5;
    const int jgf = cta * JPC + jlf;

    for (int t = 0; t < T_STEPS; ++t) {
        const float* hcur = g_h[t & 1];
        float* hnext = g_h[(t & 1) ^ 1];

        float xr = 0.f, xz = 0.f, xn = 0.f, rv = 0.f;
        if (tid < JPC * B_DIM) {
            size_t base = (size_t)t * (G_DIM * B_DIM);
            xr = xg[base + (size_t)(0 * H_DIM + jgf) * B_DIM + lane];
            xz = xg[base + (size_t)(1 * H_DIM + jgf) * B_DIM + lane];
            xn = xg[base + (size_t)(2 * H_DIM + jgf) * B_DIM + lane];
            if (res)
                rv = res[(size_t)(T_STEPS - 1 - t) * (H_DIM * B_DIM) +
                         (size_t)jgf * B_DIM + lane];
        }

#pragma unroll
        for (int i = 0; i < 16; ++i) {
            int idx = (i * NTHREADS + tid) * 4;
            *(float4*)&h_s[idx] = *(const float4*)&hcur[idx];
        }
        __syncthreads();

        float a0 = 0.f, a1 = 0.f, a2 = 0.f, a3 = 0.f, a4 = 0.f, a5 = 0.f;
        const float* hp = &h_s[kbase * B_DIM + lane];
#pragma unroll 4
        for (int k = 0; k < KQL; k += 4) {
            float h0 = hp[(k + 0) * B_DIM];
            float h1 = hp[(k + 1) * B_DIM];
            float h2 = hp[(k + 2) * B_DIM];
            float h3 = hp[(k + 3) * B_DIM];
            float4 v0 = *(const float4*)(w0 + kbase + k);
            float4 v1 = *(const float4*)(w1 + kbase + k);
            float4 v2 = *(const float4*)(w2 + kbase + k);
            float4 v3 = *(const float4*)(w3 + kbase + k);
            float4 v4 = *(const float4*)(w4 + kbase + k);
            float4 v5 = *(const float4*)(w5 + kbase + k);
            a0 = fmaf(h0, v0.x, a0); a0 = fmaf(h1, v0.y, a0); a0 = fmaf(h2, v0.z, a0); a0 = fmaf(h3, v0.w, a0);
            a1 = fmaf(h0, v1.x, a1); a1 = fmaf(h1, v1.y, a1); a1 = fmaf(h2, v1.z, a1); a1 = fmaf(h3, v1.w, a1);
            a2 = fmaf(h0, v2.x, a2); a2 = fmaf(h1, v2.y, a2); a2 = fmaf(h2, v2.z, a2); a2 = fmaf(h3, v2.w, a2);
            a3 = fmaf(h0, v3.x, a3); a3 = fmaf(h1, v3.y, a3); a3 = fmaf(h2, v3.z, a3); a3 = fmaf(h3, v3.w, a3);
            a4 = fmaf(h0, v4.x, a4); a4 = fmaf(h1, v4.y, a4); a4 = fmaf(h2, v4.z, a4); a4 = fmaf(h3, v4.w, a4);
            a5 = fmaf(h0, v5.x, a5); a5 = fmaf(h1, v5.y, a5); a5 = fmaf(h2, v5.z, a5); a5 = fmaf(h3, v5.w, a5);
        }
        part[((j0 * 3 + 0) * 4 + kq) * B_DIM + lane] = a0;
        part[((j0 * 3 + 1) * 4 + kq) * B_DIM + lane] = a1;
        part[((j0 * 3 + 2) * 4 + kq) * B_DIM + lane] = a2;
        part[((j1 * 3 + 0) * 4 + kq) * B_DIM + lane] = a3;
        part[((j1 * 3 + 1) * 4 + kq) * B_DIM + lane] = a4;
        part[((j1 * 3 + 2) * 4 + kq) * B_DIM + lane] = a5;
        __syncthreads();

        if (tid < JPC * B_DIM) {
            const float* p = &part[(jlf * 3) * 4 * B_DIM + lane];
            float hr = p[0 * B_DIM] + p[1 * B_DIM] + p[2 * B_DIM] + p[3 * B_DIM];
            float hz = p[4 * B_DIM] + p[5 * B_DIM] + p[6 * B_DIM] + p[7 * B_DIM];
            float hn = p[8 * B_DIM] + p[9 * B_DIM] + p[10 * B_DIM] + p[11 * B_DIM];
            hr += bsh[jlf * 3 + 0];
            hz += bsh[jlf * 3 + 1];
            hn += bsh[jlf * 3 + 2];
            float r = 1.f / (1.f + expf(-(xr + hr)));
            float z = 1.f / (1.f + expf(-(xz + hz)));
            float n = tanhf(xn + r * hn);
            float hprev = h_s[jgf * B_DIM + lane];
            float hv = (1.f - z) * n + z * hprev;
            hnext[jgf * B_DIM + lane] = hv;
            float ov = rv + hv;
            if (out_mode == 0)
                out[(size_t)t * (H_DIM * B_DIM) + (size_t)jgf * B_DIM + lane] = ov;
            else
                out[((size_t)lane * T_STEPS + (T_STEPS - 1 - t)) * H_DIM + jgf] = ov;
        }
        __threadfence();
        grid_barrier();
    }
}

// ---------------- host launcher ----------------
extern "C" void kernel_launch(void* const* d_in, const int* in_sizes, int n_in,
                              void* d_out, int out_size) {
    const float* x    = (const float*)d_in[0];
    const float* Wih0 = (const float*)d_in[1];
    const float* Whh0 = (const float*)d_in[2];
    const float* bih0 = (const float*)d_in[3];
    const float* bhh0 = (const float*)d_in[4];
    const float* WihS = (const float*)d_in[5];
    const float* WhhS = (const float*)d_in[6];
    const float* bihS = (const float*)d_in[7];
    const float* bhhS = (const float*)d_in[8];
    float* out = (float*)d_out;

    float *xgP, *actA, *actB;
    __nv_bfloat16 *AbigP, *WbigP;
    cudaGetSymbolAddress((void**)&xgP, g_xg);
    cudaGetSymbolAddress((void**)&actA, g_actA);
    cudaGetSymbolAddress((void**)&actB, g_actB);
    cudaGetSymbolAddress((void**)&AbigP, g_Abig);
    cudaGetSymbolAddress((void**)&WbigP, g_Wbig);

    cudaFuncSetAttribute(gru_recurrent, cudaFuncAttributeMaxDynamicSharedMemorySize,
                         (int)SMEM_REC);
    const int GEMM_SMEM = (NSTAGES * STAGE_ELEMS * 2 > 8 * 64 * 33 * 4)
                        ? NSTAGES * STAGE_ELEMS * 2 : 8 * 64 * 33 * 4;
    cudaFuncSetAttribute(gemm_tc, cudaFuncAttributeMaxDynamicSharedMemorySize, GEMM_SMEM);

    // split all W_ih into bf16 hi/lo layout (once per call)
    {
        int nblk = (G_DIM * H_DIM + 255) / 256;
        split_w<<<nblk, 256>>>(Wih0, WbigP);
        for (int l = 1; l < 4; ++l)
            split_w<<<nblk, 256>>>(WihS + (size_t)(l - 1) * G_DIM * H_DIM,
                                   WbigP + (size_t)l * G_DIM * KBIG);
    }

    for (int l = 0; l < 4; ++l) {
        const float* bih = (l == 0) ? bih0 : bihS + (size_t)(l - 1) * G_DIM;
        const float* Whh = (l == 0) ? Whh0 : WhhS + (size_t)(l - 1) * G_DIM * H_DIM;
        const float* bhh = (l == 0) ? bhh0 : bhhS + (size_t)(l - 1) * G_DIM;

        const float* ain = (l & 1) ? actB : actA;
        float* aout = (l == 3) ? out : ((l & 1) ? actA : actB);

        if (l == 0)
            split_x0<<<T_STEPS, 256>>>(x, AbigP);
        else
            split_act<<<dim3(T_STEPS, H_DIM / 64), 256>>>(ain, AbigP);

        gemm_tc<<<dim3(G_DIM / 128, M_BIG / 128), 256, GEMM_SMEM>>>(
            AbigP, WbigP + (size_t)l * G_DIM * KBIG, bih, xgP);

        gru_recurrent<<<NCTAS, NTHREADS, SMEM_REC>>>(
            Whh, bhh, xgP, (l == 0) ? nullptr : ain, aout, (l == 3) ? 1 : 0);
    }
}

// round 5
// speedup vs baseline: 1.5299x; 1.3276x over previous
#include <cuda_runtime.h>
#include <cuda_bf16.h>
#include <cstdint>

#define T_STEPS 1024
#define H_DIM   768
#define B_DIM   32
#define G_DIM   (3*H_DIM)     // 2304
#define KBIG    2304          // 3 x 768 (split-K bf16 precision scheme)
#define M_BIG   (T_STEPS*B_DIM) // 32768

// ---------------- static device scratch ----------------
__device__ float g_xg[(size_t)T_STEPS * G_DIM * B_DIM];
__device__ float g_actA[(size_t)T_STEPS * H_DIM * B_DIM];
__device__ float g_actB[(size_t)T_STEPS * H_DIM * B_DIM];
__device__ __align__(1024) __nv_bfloat16 g_Abig[(size_t)M_BIG * KBIG];
__device__ __align__(1024) __nv_bfloat16 g_Wbig[(size_t)4 * G_DIM * KBIG];    // W_ih split
__device__ __align__(1024) __nv_bfloat16 g_WhhBig[(size_t)4 * G_DIM * KBIG];  // W_hh split
__device__ __align__(256) __nv_bfloat16 g_hs[2][1536 * B_DIM];  // h split hi(0-767)/lo(768-1535), [k][b]
__device__ unsigned int g_arrive = 0;
__device__ volatile unsigned int g_gen = 0;

// ---------------- software grid barrier ----------------
__device__ __forceinline__ void grid_barrier() {
    __syncthreads();
    if (threadIdx.x == 0) {
        unsigned int target = gridDim.x;
        __threadfence();
        unsigned int gen = g_gen;
        if (atomicAdd(&g_arrive, 1) == target - 1) {
            atomicExch(&g_arrive, 0);
            __threadfence();
            g_gen = gen + 1;
        } else {
            while (g_gen == gen) { }
            __threadfence();
        }
    }
    __syncthreads();
}

// ---------------- bf16 two-term split helpers ----------------
__device__ __forceinline__ void split_bf16(float v, __nv_bfloat16& hi, __nv_bfloat16& lo) {
    hi = __float2bfloat16(v);
    lo = __float2bfloat16(v - __bfloat162float(hi));
}

__global__ void __launch_bounds__(256) split_x0(const float* __restrict__ x,
                                                __nv_bfloat16* __restrict__ Ab) {
    int t = blockIdx.x;
    for (int i = threadIdx.x; i < 32 * H_DIM; i += 256) {
        int b = i / H_DIM, d = i % H_DIM;
        float v = x[((size_t)b * T_STEPS + t) * H_DIM + d];
        __nv_bfloat16 hi, lo; split_bf16(v, hi, lo);
        size_t r = ((size_t)t * 32 + b) * KBIG;
        Ab[r + d] = hi;
        Ab[r + 768 + d] = lo;
        Ab[r + 1536 + d] = hi;
    }
}

__global__ void __launch_bounds__(256) split_act(const float* __restrict__ act,
                                                 __nv_bfloat16* __restrict__ Ab) {
    __shared__ float sm[64][33];
    int t = blockIdx.x;
    int d0 = blockIdx.y * 64;
    int ts = T_STEPS - 1 - t;
    for (int i = threadIdx.x; i < 64 * 32; i += 256) {
        int dl = i >> 5, b = i & 31;
        sm[dl][b] = act[((size_t)ts * H_DIM + d0 + dl) * B_DIM + b];
    }
    __syncthreads();
    for (int i = threadIdx.x; i < 32 * 64; i += 256) {
        int b = i >> 6, dl = i & 63;
        float v = sm[dl][b];
        __nv_bfloat16 hi, lo; split_bf16(v, hi, lo);
        size_t r = ((size_t)t * 32 + b) * KBIG;
        Ab[r + d0 + dl] = hi;
        Ab[r + 768 + d0 + dl] = lo;
        Ab[r + 1536 + d0 + dl] = hi;
    }
}

__global__ void __launch_bounds__(256) split_w(const float* __restrict__ W,
                                               __nv_bfloat16* __restrict__ Wb) {
    int i = blockIdx.x * 256 + threadIdx.x;
    if (i >= G_DIM * H_DIM) return;
    int g = i / H_DIM, d = i % H_DIM;
    float v = W[i];
    __nv_bfloat16 hi, lo; split_bf16(v, hi, lo);
    size_t r = (size_t)g * KBIG;
    Wb[r + d] = hi;
    Wb[r + 768 + d] = hi;
    Wb[r + 1536 + d] = lo;
}

// ---------------- common asm helpers ----------------
__device__ __forceinline__ void cp16(void* s, const void* g) {
    uint32_t sa = (uint32_t)__cvta_generic_to_shared(s);
    asm volatile("cp.async.cg.shared.global [%0], [%1], 16;\n" :: "r"(sa), "l"(g));
}
__device__ __forceinline__ void cp16a(uint32_t sa, const void* g) {
    asm volatile("cp.async.cg.shared.global [%0], [%1], 16;\n" :: "r"(sa), "l"(g));
}
__device__ __forceinline__ void ldsm_x4(uint32_t& r0, uint32_t& r1, uint32_t& r2, uint32_t& r3,
                                        const __nv_bfloat16* p) {
    uint32_t a = (uint32_t)__cvta_generic_to_shared(p);
    asm volatile("ldmatrix.sync.aligned.m8n8.x4.shared.b16 {%0,%1,%2,%3}, [%4];\n"
                 : "=r"(r0), "=r"(r1), "=r"(r2), "=r"(r3) : "r"(a));
}
__device__ __forceinline__ void ldsm_x4a(uint32_t& r0, uint32_t& r1, uint32_t& r2, uint32_t& r3,
                                         uint32_t a) {
    asm volatile("ldmatrix.sync.aligned.m8n8.x4.shared.b16 {%0,%1,%2,%3}, [%4];\n"
                 : "=r"(r0), "=r"(r1), "=r"(r2), "=r"(r3) : "r"(a));
}
__device__ __forceinline__ void ldsm_x4t(uint32_t& r0, uint32_t& r1, uint32_t& r2, uint32_t& r3,
                                         uint32_t a) {
    asm volatile("ldmatrix.sync.aligned.m8n8.x4.trans.shared.b16 {%0,%1,%2,%3}, [%4];\n"
                 : "=r"(r0), "=r"(r1), "=r"(r2), "=r"(r3) : "r"(a));
}
__device__ __forceinline__ void mma_bf16(float* c, const uint32_t* a, const uint32_t* b) {
    asm volatile("mma.sync.aligned.m16n8k16.row.col.f32.bf16.bf16.f32 "
                 "{%0,%1,%2,%3}, {%4,%5,%6,%7}, {%8,%9}, {%0,%1,%2,%3};\n"
                 : "+f"(c[0]), "+f"(c[1]), "+f"(c[2]), "+f"(c[3])
                 : "r"(a[0]), "r"(a[1]), "r"(a[2]), "r"(a[3]), "r"(b[0]), "r"(b[1]));
}

// ---------------- input-projection GEMM (R3, mma.sync) ----------------
#define GBK 32
#define SPITCH 40
#define ASZ (128 * SPITCH)
#define STAGE_ELEMS (2 * ASZ)
#define NSTAGES 3
#define KTILES (KBIG / GBK)

__global__ void __launch_bounds__(256) gemm_tc(
    const __nv_bfloat16* __restrict__ A,
    const __nv_bfloat16* __restrict__ Wb,
    const float* __restrict__ bias,
    float* __restrict__ xg)
{
    extern __shared__ char smem_raw[];
    __nv_bfloat16* sm = (__nv_bfloat16*)smem_raw;

    const int tid = threadIdx.x;
    const int lane = tid & 31;
    const int warp = tid >> 5;
    const int wm = warp >> 1;
    const int wn = warp & 1;
    const int gBase = blockIdx.x * 128;
    const int mBase = blockIdx.y * 128;

    float acc[2][8][4];
#pragma unroll
    for (int i = 0; i < 2; ++i)
#pragma unroll
        for (int j = 0; j < 8; ++j)
#pragma unroll
            for (int k = 0; k < 4; ++k) acc[i][j][k] = 0.f;

    auto load_tile = [&](int stage, int kt) {
        __nv_bfloat16* As = sm + stage * STAGE_ELEMS;
        __nv_bfloat16* Bs = As + ASZ;
        int k0 = kt * GBK;
#pragma unroll
        for (int i = 0; i < 2; ++i) {
            int task = i * 256 + tid;
            int row = task >> 2, ch = task & 3;
            cp16(As + row * SPITCH + ch * 8,
                 A + (size_t)(mBase + row) * KBIG + k0 + ch * 8);
            cp16(Bs + row * SPITCH + ch * 8,
                 Wb + (size_t)(gBase + row) * KBIG + k0 + ch * 8);
        }
    };

#pragma unroll
    for (int s = 0; s < NSTAGES; ++s) {
        load_tile(s, s);
        asm volatile("cp.async.commit_group;\n" ::: "memory");
    }

    for (int kt = 0; kt < KTILES; ++kt) {
        asm volatile("cp.async.wait_group %0;\n" :: "n"(NSTAGES - 1) : "memory");
        __syncthreads();
        int s = kt % NSTAGES;
        const __nv_bfloat16* As = sm + s * STAGE_ELEMS;
        const __nv_bfloat16* Bs = As + ASZ;

#pragma unroll
        for (int kk = 0; kk < 2; ++kk) {
            uint32_t af[2][4];
            uint32_t bf[8][2];
#pragma unroll
            for (int mt = 0; mt < 2; ++mt) {
                const __nv_bfloat16* p = As + (wm * 32 + mt * 16 + (lane & 15)) * SPITCH
                                            + kk * 16 + (lane >> 4) * 8;
                ldsm_x4(af[mt][0], af[mt][1], af[mt][2], af[mt][3], p);
            }
#pragma unroll
            for (int np = 0; np < 4; ++np) {
                int grp = lane >> 3;
                const __nv_bfloat16* p = Bs + (wn * 64 + np * 16 + (grp >> 1) * 8 + (lane & 7)) * SPITCH
                                            + kk * 16 + (grp & 1) * 8;
                uint32_t r0, r1, r2, r3;
                ldsm_x4(r0, r1, r2, r3, p);
                bf[2 * np][0] = r0; bf[2 * np][1] = r1;
                bf[2 * np + 1][0] = r2; bf[2 * np + 1][1] = r3;
            }
#pragma unroll
            for (int mt = 0; mt < 2; ++mt)
#pragma unroll
                for (int nt = 0; nt < 8; ++nt)
                    mma_bf16(acc[mt][nt], af[mt], bf[nt]);
        }
        __syncthreads();
        int ktn = kt + NSTAGES;
        if (ktn < KTILES) load_tile(ktn % NSTAGES, ktn);
        asm volatile("cp.async.commit_group;\n" ::: "memory");
    }
    asm volatile("cp.async.wait_all;\n" ::: "memory");
    __syncthreads();

    float* ebuf = (float*)smem_raw + warp * (64 * 33);
#pragma unroll
    for (int mt = 0; mt < 2; ++mt)
#pragma unroll
        for (int nt = 0; nt < 8; ++nt) {
            int b0 = mt * 16 + (lane >> 2);
            int gl = nt * 8 + (lane & 3) * 2;
            ebuf[gl * 33 + b0]            = acc[mt][nt][0];
            ebuf[(gl + 1) * 33 + b0]      = acc[mt][nt][1];
            ebuf[gl * 33 + b0 + 8]        = acc[mt][nt][2];
            ebuf[(gl + 1) * 33 + b0 + 8]  = acc[mt][nt][3];
        }
    __syncwarp();
    int t = blockIdx.y * 4 + wm;
    int g0 = gBase + wn * 64;
    size_t obase = (size_t)t * (G_DIM * B_DIM);
#pragma unroll 4
    for (int g = 0; g < 64; ++g) {
        xg[obase + (size_t)(g0 + g) * B_DIM + lane] = ebuf[g * 33 + lane] + bias[g0 + g];
    }
}

// ================= tensor-core recurrent kernel =================
// 96 CTAs x 384 threads. CTA owns 8 hidden units (24 gate rows).
// mma: M=32 (batch, 2 mtiles), N=24 (3 ntiles of 8), K=2304 (144 ktiles, 3-term split).
// 12 warps = 3 ntiles x 4 k-quarters (36 ktiles each).
#define RCTAS 96
#define RTHR  384
#define WPITCH 2312                      // bf16 per W smem row (+8 pad -> conflict-free ldsm)
#define SM_W_BYTES (24 * WPITCH * 2)     // 110976
#define SM_H_OFF   SM_W_BYTES            // 128B-aligned (110976 = 867*128)
#define SM_H_BYTES (1536 * 64)           // 98304: h split [k][32b] with xor-swizzled 16B chunks
#define SM_PART_OFF (SM_H_OFF + SM_H_BYTES)      // 209280
#define SM_PART_BYTES (12 * 2 * 4 * 32 * 4)      // 12288
#define SM_BSH_OFF (SM_PART_OFF + SM_PART_BYTES) // 221568
#define SM_REC_TOTAL (SM_BSH_OFF + 128)          // 221696

// swizzled 16B-chunk index for h_s: row k (64B = 4 chunks), chunk c (m-group)
__device__ __forceinline__ uint32_t hs_chunk(int k, int c) {
    return (uint32_t)((k >> 1) * 8 + ((((k & 1) << 2) | c) ^ ((k >> 1) & 7)));
}

__global__ void __launch_bounds__(RTHR, 1) gru_rec_tc(
    const __nv_bfloat16* __restrict__ WhhB,  // [2304][2304] split
    const float* __restrict__ bhh,           // [2304]
    const float* __restrict__ xg,            // [t][g][b]
    const float* __restrict__ res,           // prev act [t][d][b] or null
    float* __restrict__ out,
    int out_mode)
{
    extern __shared__ __align__(1024) char smr[];
    __nv_bfloat16* Wsm = (__nv_bfloat16*)smr;
    const uint32_t hs_base = (uint32_t)__cvta_generic_to_shared(smr + SM_H_OFF);
    float* part = (float*)(smr + SM_PART_OFF);
    float* bsh  = (float*)(smr + SM_BSH_OFF);

    const int tid = threadIdx.x;
    const int lane = tid & 31;
    const int w = tid >> 5;           // 0..11
    const int kq = w & 3;             // k-quarter
    const int nt = w >> 2;            // gate tile 0..2
    const int cta = blockIdx.x;

    // ---- load W_hh slice into smem (rows n = gt*8+jl <- global gt*768 + cta*8 + jl) ----
#pragma unroll
    for (int i = 0; i < 18; ++i) {
        int task = i * RTHR + tid;            // 6912 = 24 rows x 288 chunks
        int n = task / 288, c = task % 288;
        int grow = (n >> 3) * H_DIM + cta * 8 + (n & 7);
        cp16(Wsm + n * WPITCH + c * 8, WhhB + (size_t)grow * KBIG + c * 8);
    }
    if (tid < 24) {
        int gt = tid >> 3, jl = tid & 7;
        bsh[tid] = bhh[gt * H_DIM + cta * 8 + jl];
    }
    if (tid < 256) {
        int jl = tid >> 5, j = cta * 8 + jl;
        g_hs[0][j * B_DIM + lane] = __float2bfloat16(0.f);
        g_hs[0][(768 + j) * B_DIM + lane] = __float2bfloat16(0.f);
    }
    asm volatile("cp.async.commit_group;\n" ::: "memory");
    asm volatile("cp.async.wait_all;\n" ::: "memory");
    __threadfence();
    grid_barrier();

    // ---- per-thread ldsm address components ----
    const int t4 = lane >> 3, r8 = lane & 7;
    const uint32_t w_base = (uint32_t)__cvta_generic_to_shared(Wsm)
                          + (uint32_t)((nt * 8 + r8) * WPITCH * 2 + t4 * 16);
    // A addr for (kt, mt): krow = hrow(kt) + (t4>>1)*8 + r8, c = mt*2 + (t4&1)
    const int a_roff = ((t4 >> 1) << 3) + r8;
    const int a_c0 = (t4 & 1);

    auto a_addr = [&](int kt, int mt) -> uint32_t {
        int hrow = (kt < 96 ? kt : kt - 96) << 4;
        int krow = hrow + a_roff;
        int c = mt * 2 + a_c0;
        return hs_base + hs_chunk(krow, c) * 16;
    };

    const int ktstart = kq * 36;
    const int jlf = tid >> 5;             // finalize unit (tid<256)
    const int jgf = cta * 8 + jlf;
    const int mtF = lane >> 4, m_in = lane & 15;
    const int lane_src = (m_in & 7) * 4 + (jlf >> 1);
    const int regF = (jlf & 1) + 2 * (m_in >> 3);
    float hprev = 0.f;

    for (int t = 0; t < T_STEPS; ++t) {
        // prefetch xg + residual (independent of h)
        float xr = 0.f, xz = 0.f, xn = 0.f, rv = 0.f;
        if (tid < 256) {
            size_t base = (size_t)t * (G_DIM * B_DIM);
            xr = xg[base + (size_t)(0 * H_DIM + jgf) * B_DIM + lane];
            xz = xg[base + (size_t)(1 * H_DIM + jgf) * B_DIM + lane];
            xn = xg[base + (size_t)(2 * H_DIM + jgf) * B_DIM + lane];
            if (res)
                rv = res[(size_t)(T_STEPS - 1 - t) * (H_DIM * B_DIM) +
                         (size_t)jgf * B_DIM + lane];
        }

        // stage h split into swizzled smem: 1536 rows x 4 chunks = 6144 tasks
        const __nv_bfloat16* hsrc = g_hs[t & 1];
#pragma unroll
        for (int i = 0; i < 16; ++i) {
            int task = i * RTHR + tid;
            int k = task >> 2, c = task & 3;
            cp16a(hs_base + hs_chunk(k, c) * 16, hsrc + k * B_DIM + c * 8);
        }
        asm volatile("cp.async.commit_group;\n" ::: "memory");
        asm volatile("cp.async.wait_all;\n" ::: "memory");
        __syncthreads();

        // ---- mma over 36 ktiles (18 pairs) ----
        float acc0[4] = {0.f, 0.f, 0.f, 0.f};
        float acc1[4] = {0.f, 0.f, 0.f, 0.f};
        uint32_t a0addr = a_addr(ktstart, 0);
        uint32_t a1addr = a_addr(ktstart, 1);
        uint32_t baddr = w_base + (uint32_t)(ktstart * 32);
#pragma unroll 2
        for (int ktp = 0; ktp < 18; ++ktp) {
            int kt0 = ktstart + ktp * 2;
            if (kt0 == 96) { a0addr = a_addr(96, 0); a1addr = a_addr(96, 1); }
            uint32_t b0, b1, b2, b3;
            ldsm_x4a(b0, b1, b2, b3, baddr);
            uint32_t bA[2] = {b0, b1}, bB[2] = {b2, b3};
            uint32_t af[4];
            ldsm_x4t(af[0], af[1], af[2], af[3], a0addr);
            mma_bf16(acc0, af, bA);
            ldsm_x4t(af[0], af[1], af[2], af[3], a1addr);
            mma_bf16(acc1, af, bA);
            a0addr += 1024; a1addr += 1024;
            ldsm_x4t(af[0], af[1], af[2], af[3], a0addr);
            mma_bf16(acc0, af, bB);
            ldsm_x4t(af[0], af[1], af[2], af[3], a1addr);
            mma_bf16(acc1, af, bB);
            a0addr += 1024; a1addr += 1024;
            baddr += 64;
        }
        // write partials: part[((w*2+mt)*4+reg)*32 + lane]
#pragma unroll
        for (int rg = 0; rg < 4; ++rg) {
            part[((w * 2 + 0) * 4 + rg) * 32 + lane] = acc0[rg];
            part[((w * 2 + 1) * 4 + rg) * 32 + lane] = acc1[rg];
        }
        __syncthreads();

        // ---- finalize: 256 threads = 8 units x 32 batch ----
        if (tid < 256) {
            float g3[3];
#pragma unroll
            for (int gt = 0; gt < 3; ++gt) {
                float s = 0.f;
#pragma unroll
                for (int k4 = 0; k4 < 4; ++k4) {
                    int wsrc = gt * 4 + k4;
                    s += part[((wsrc * 2 + mtF) * 4 + regF) * 32 + lane_src];
                }
                g3[gt] = s + bsh[gt * 8 + jlf];
            }
            float r = 1.f / (1.f + expf(-(xr + g3[0])));
            float z = 1.f / (1.f + expf(-(xz + g3[1])));
            float n = tanhf(xn + r * g3[2]);
            float hv = (1.f - z) * n + z * hprev;
            hprev = hv;
            __nv_bfloat16 hi, lo; split_bf16(hv, hi, lo);
            __nv_bfloat16* hdst = g_hs[(t & 1) ^ 1];
            hdst[jgf * B_DIM + lane] = hi;
            hdst[(768 + jgf) * B_DIM + lane] = lo;
            float ov = rv + hv;
            if (out_mode == 0)
                out[(size_t)t * (H_DIM * B_DIM) + (size_t)jgf * B_DIM + lane] = ov;
            else
                out[((size_t)lane * T_STEPS + (T_STEPS - 1 - t)) * H_DIM + jgf] = ov;
        }
        __threadfence();
        grid_barrier();
    }
}

// ---------------- host launcher ----------------
extern "C" void kernel_launch(void* const* d_in, const int* in_sizes, int n_in,
                              void* d_out, int out_size) {
    const float* x    = (const float*)d_in[0];
    const float* Wih0 = (const float*)d_in[1];
    const float* Whh0 = (const float*)d_in[2];
    const float* bih0 = (const float*)d_in[3];
    const float* bhh0 = (const float*)d_in[4];
    const float* WihS = (const float*)d_in[5];
    const float* WhhS = (const float*)d_in[6];
    const float* bihS = (const float*)d_in[7];
    const float* bhhS = (const float*)d_in[8];
    float* out = (float*)d_out;

    float *xgP, *actA, *actB;
    __nv_bfloat16 *AbigP, *WbigP, *WhhBigP;
    cudaGetSymbolAddress((void**)&xgP, g_xg);
    cudaGetSymbolAddress((void**)&actA, g_actA);
    cudaGetSymbolAddress((void**)&actB, g_actB);
    cudaGetSymbolAddress((void**)&AbigP, g_Abig);
    cudaGetSymbolAddress((void**)&WbigP, g_Wbig);
    cudaGetSymbolAddress((void**)&WhhBigP, g_WhhBig);

    const int GEMM_SMEM = (NSTAGES * STAGE_ELEMS * 2 > 8 * 64 * 33 * 4)
                        ? NSTAGES * STAGE_ELEMS * 2 : 8 * 64 * 33 * 4;
    cudaFuncSetAttribute(gemm_tc, cudaFuncAttributeMaxDynamicSharedMemorySize, GEMM_SMEM);
    cudaFuncSetAttribute(gru_rec_tc, cudaFuncAttributeMaxDynamicSharedMemorySize,
                         (int)SM_REC_TOTAL);

    // split all weights into bf16 hi/lo layout
    {
        int nblk = (G_DIM * H_DIM + 255) / 256;
        split_w<<<nblk, 256>>>(Wih0, WbigP);
        split_w<<<nblk, 256>>>(Whh0, WhhBigP);
        for (int l = 1; l < 4; ++l) {
            split_w<<<nblk, 256>>>(WihS + (size_t)(l - 1) * G_DIM * H_DIM,
                                   WbigP + (size_t)l * G_DIM * KBIG);
            split_w<<<nblk, 256>>>(WhhS + (size_t)(l - 1) * G_DIM * H_DIM,
                                   WhhBigP + (size_t)l * G_DIM * KBIG);
        }
    }

    for (int l = 0; l < 4; ++l) {
        const float* bih = (l == 0) ? bih0 : bihS + (size_t)(l - 1) * G_DIM;
        const float* bhh = (l == 0) ? bhh0 : bhhS + (size_t)(l - 1) * G_DIM;

        const float* ain = (l & 1) ? actB : actA;
        float* aout = (l == 3) ? out : ((l & 1) ? actA : actB);

        if (l == 0)
            split_x0<<<T_STEPS, 256>>>(x, AbigP);
        else
            split_act<<<dim3(T_STEPS, H_DIM / 64), 256>>>(ain, AbigP);

        gemm_tc<<<dim3(G_DIM / 128, M_BIG / 128), 256, GEMM_SMEM>>>(
            AbigP, WbigP + (size_t)l * G_DIM * KBIG, bih, xgP);

        gru_rec_tc<<<RCTAS, RTHR, SM_REC_TOTAL>>>(
            WhhBigP + (size_t)l * G_DIM * KBIG, bhh, xgP,
            (l == 0) ? nullptr : ain, aout, (l == 3) ? 1 : 0);
    }
}

// round 6
// speedup vs baseline: 1.6362x; 1.0695x over previous
#include <cuda_runtime.h>
#include <cuda_bf16.h>
#include <cstdint>

#define T_STEPS 1024
#define H_DIM   768
#define B_DIM   32
#define G_DIM   (3*H_DIM)     // 2304
#define KBIG    2304          // 3 x 768 (split-K bf16 precision scheme)
#define M_BIG   (T_STEPS*B_DIM) // 32768

// ---------------- static device scratch ----------------
__device__ float g_xg[(size_t)T_STEPS * G_DIM * B_DIM];
__device__ float g_actA[(size_t)T_STEPS * H_DIM * B_DIM];
__device__ float g_actB[(size_t)T_STEPS * H_DIM * B_DIM];
__device__ __align__(1024) __nv_bfloat16 g_Abig[(size_t)M_BIG * KBIG];
__device__ __align__(1024) __nv_bfloat16 g_Wbig[(size_t)4 * G_DIM * KBIG];    // W_ih split
__device__ __align__(1024) __nv_bfloat16 g_WhhBig[(size_t)4 * G_DIM * KBIG];  // W_hh split
__device__ __align__(256) __nv_bfloat16 g_hs[2][1536 * B_DIM];  // h split hi/lo, [k][b]
__device__ unsigned int g_arrive = 0;
__device__ volatile unsigned int g_gen = 0;

// ---------------- software grid barrier ----------------
__device__ __forceinline__ void grid_barrier() {
    __syncthreads();
    if (threadIdx.x == 0) {
        unsigned int target = gridDim.x;
        __threadfence();
        unsigned int gen = g_gen;
        if (atomicAdd(&g_arrive, 1) == target - 1) {
            atomicExch(&g_arrive, 0);
            __threadfence();
            g_gen = gen + 1;
        } else {
            while (g_gen == gen) { }
            __threadfence();
        }
    }
    __syncthreads();
}

// ---------------- bf16 two-term split helpers ----------------
__device__ __forceinline__ void split_bf16(float v, __nv_bfloat16& hi, __nv_bfloat16& lo) {
    hi = __float2bfloat16(v);
    lo = __float2bfloat16(v - __bfloat162float(hi));
}

__global__ void __launch_bounds__(256) split_x0(const float* __restrict__ x,
                                                __nv_bfloat16* __restrict__ Ab) {
    int t = blockIdx.x;
    for (int i = threadIdx.x; i < 32 * H_DIM; i += 256) {
        int b = i / H_DIM, d = i % H_DIM;
        float v = x[((size_t)b * T_STEPS + t) * H_DIM + d];
        __nv_bfloat16 hi, lo; split_bf16(v, hi, lo);
        size_t r = ((size_t)t * 32 + b) * KBIG;
        Ab[r + d] = hi;
        Ab[r + 768 + d] = lo;
        Ab[r + 1536 + d] = hi;
    }
}

__global__ void __launch_bounds__(256) split_act(const float* __restrict__ act,
                                                 __nv_bfloat16* __restrict__ Ab) {
    __shared__ float sm[64][33];
    int t = blockIdx.x;
    int d0 = blockIdx.y * 64;
    int ts = T_STEPS - 1 - t;
    for (int i = threadIdx.x; i < 64 * 32; i += 256) {
        int dl = i >> 5, b = i & 31;
        sm[dl][b] = act[((size_t)ts * H_DIM + d0 + dl) * B_DIM + b];
    }
    __syncthreads();
    for (int i = threadIdx.x; i < 32 * 64; i += 256) {
        int b = i >> 6, dl = i & 63;
        float v = sm[dl][b];
        __nv_bfloat16 hi, lo; split_bf16(v, hi, lo);
        size_t r = ((size_t)t * 32 + b) * KBIG;
        Ab[r + d0 + dl] = hi;
        Ab[r + 768 + d0 + dl] = lo;
        Ab[r + 1536 + d0 + dl] = hi;
    }
}

__global__ void __launch_bounds__(256) split_w(const float* __restrict__ W,
                                               __nv_bfloat16* __restrict__ Wb) {
    int i = blockIdx.x * 256 + threadIdx.x;
    if (i >= G_DIM * H_DIM) return;
    int g = i / H_DIM, d = i % H_DIM;
    float v = W[i];
    __nv_bfloat16 hi, lo; split_bf16(v, hi, lo);
    size_t r = (size_t)g * KBIG;
    Wb[r + d] = hi;
    Wb[r + 768 + d] = hi;
    Wb[r + 1536 + d] = lo;
}

// ---------------- common asm helpers ----------------
__device__ __forceinline__ void cp16(void* s, const void* g) {
    uint32_t sa = (uint32_t)__cvta_generic_to_shared(s);
    asm volatile("cp.async.cg.shared.global [%0], [%1], 16;\n" :: "r"(sa), "l"(g));
}
__device__ __forceinline__ void cp16a(uint32_t sa, const void* g) {
    asm volatile("cp.async.cg.shared.global [%0], [%1], 16;\n" :: "r"(sa), "l"(g));
}
__device__ __forceinline__ void ldsm_x4(uint32_t& r0, uint32_t& r1, uint32_t& r2, uint32_t& r3,
                                        const __nv_bfloat16* p) {
    uint32_t a = (uint32_t)__cvta_generic_to_shared(p);
    asm volatile("ldmatrix.sync.aligned.m8n8.x4.shared.b16 {%0,%1,%2,%3}, [%4];\n"
                 : "=r"(r0), "=r"(r1), "=r"(r2), "=r"(r3) : "r"(a));
}
__device__ __forceinline__ void ldsm_x4a(uint32_t& r0, uint32_t& r1, uint32_t& r2, uint32_t& r3,
                                         uint32_t a) {
    asm volatile("ldmatrix.sync.aligned.m8n8.x4.shared.b16 {%0,%1,%2,%3}, [%4];\n"
                 : "=r"(r0), "=r"(r1), "=r"(r2), "=r"(r3) : "r"(a));
}
__device__ __forceinline__ void ldsm_x4t(uint32_t& r0, uint32_t& r1, uint32_t& r2, uint32_t& r3,
                                         uint32_t a) {
    asm volatile("ldmatrix.sync.aligned.m8n8.x4.trans.shared.b16 {%0,%1,%2,%3}, [%4];\n"
                 : "=r"(r0), "=r"(r1), "=r"(r2), "=r"(r3) : "r"(a));
}
__device__ __forceinline__ void mma_bf16(float* c, const uint32_t* a, const uint32_t* b) {
    asm volatile("mma.sync.aligned.m16n8k16.row.col.f32.bf16.bf16.f32 "
                 "{%0,%1,%2,%3}, {%4,%5,%6,%7}, {%8,%9}, {%0,%1,%2,%3};\n"
                 : "+f"(c[0]), "+f"(c[1]), "+f"(c[2]), "+f"(c[3])
                 : "r"(a[0]), "r"(a[1]), "r"(a[2]), "r"(a[3]), "r"(b[0]), "r"(b[1]));
}

// ---------------- input-projection GEMM (4-stage, single sync/iter) ----------------
#define GBK 32
#define SPITCH 40
#define ASZ (128 * SPITCH)
#define STAGE_ELEMS (2 * ASZ)
#define NSTAGES 4
#define KTILES (KBIG / GBK)   // 72

__global__ void __launch_bounds__(256) gemm_tc(
    const __nv_bfloat16* __restrict__ A,
    const __nv_bfloat16* __restrict__ Wb,
    const float* __restrict__ bias,
    float* __restrict__ xg)
{
    extern __shared__ char smem_raw[];
    __nv_bfloat16* sm = (__nv_bfloat16*)smem_raw;

    const int tid = threadIdx.x;
    const int lane = tid & 31;
    const int warp = tid >> 5;
    const int wm = warp >> 1;
    const int wn = warp & 1;
    const int gBase = blockIdx.x * 128;
    const int mBase = blockIdx.y * 128;

    float acc[2][8][4];
#pragma unroll
    for (int i = 0; i < 2; ++i)
#pragma unroll
        for (int j = 0; j < 8; ++j)
#pragma unroll
            for (int k = 0; k < 4; ++k) acc[i][j][k] = 0.f;

    auto load_tile = [&](int stage, int kt) {
        __nv_bfloat16* As = sm + stage * STAGE_ELEMS;
        __nv_bfloat16* Bs = As + ASZ;
        int k0 = kt * GBK;
#pragma unroll
        for (int i = 0; i < 2; ++i) {
            int task = i * 256 + tid;
            int row = task >> 2, ch = task & 3;
            cp16(As + row * SPITCH + ch * 8,
                 A + (size_t)(mBase + row) * KBIG + k0 + ch * 8);
            cp16(Bs + row * SPITCH + ch * 8,
                 Wb + (size_t)(gBase + row) * KBIG + k0 + ch * 8);
        }
    };

    // prologue: fill stages 0..2 (3 committed groups)
#pragma unroll
    for (int s = 0; s < 3; ++s) {
        load_tile(s, s);
        asm volatile("cp.async.commit_group;\n" ::: "memory");
    }

    for (int kt = 0; kt < KTILES; ++kt) {
        asm volatile("cp.async.wait_group %0;\n" :: "n"(2) : "memory");
        __syncthreads();
        // issue next load into stage kt+3 (its last readers finished at iter kt-1,
        // which the sync above fences)
        int ktn = kt + 3;
        if (ktn < KTILES) load_tile(ktn & 3, ktn);
        asm volatile("cp.async.commit_group;\n" ::: "memory");

        int s = kt & 3;
        const __nv_bfloat16* As = sm + s * STAGE_ELEMS;
        const __nv_bfloat16* Bs = As + ASZ;
#pragma unroll
        for (int kk = 0; kk < 2; ++kk) {
            uint32_t af[2][4];
            uint32_t bf[8][2];
#pragma unroll
            for (int mt = 0; mt < 2; ++mt) {
                const __nv_bfloat16* p = As + (wm * 32 + mt * 16 + (lane & 15)) * SPITCH
                                            + kk * 16 + (lane >> 4) * 8;
                ldsm_x4(af[mt][0], af[mt][1], af[mt][2], af[mt][3], p);
            }
#pragma unroll
            for (int np = 0; np < 4; ++np) {
                int grp = lane >> 3;
                const __nv_bfloat16* p = Bs + (wn * 64 + np * 16 + (grp >> 1) * 8 + (lane & 7)) * SPITCH
                                            + kk * 16 + (grp & 1) * 8;
                uint32_t r0, r1, r2, r3;
                ldsm_x4(r0, r1, r2, r3, p);
                bf[2 * np][0] = r0; bf[2 * np][1] = r1;
                bf[2 * np + 1][0] = r2; bf[2 * np + 1][1] = r3;
            }
#pragma unroll
            for (int mt = 0; mt < 2; ++mt)
#pragma unroll
                for (int nt = 0; nt < 8; ++nt)
                    mma_bf16(acc[mt][nt], af[mt], bf[nt]);
        }
    }
    asm volatile("cp.async.wait_all;\n" ::: "memory");
    __syncthreads();

    float* ebuf = (float*)smem_raw + warp * (64 * 33);
#pragma unroll
    for (int mt = 0; mt < 2; ++mt)
#pragma unroll
        for (int nt = 0; nt < 8; ++nt) {
            int b0 = mt * 16 + (lane >> 2);
            int gl = nt * 8 + (lane & 3) * 2;
            ebuf[gl * 33 + b0]            = acc[mt][nt][0];
            ebuf[(gl + 1) * 33 + b0]      = acc[mt][nt][1];
            ebuf[gl * 33 + b0 + 8]        = acc[mt][nt][2];
            ebuf[(gl + 1) * 33 + b0 + 8]  = acc[mt][nt][3];
        }
    __syncwarp();
    int t = blockIdx.y * 4 + wm;
    int g0 = gBase + wn * 64;
    size_t obase = (size_t)t * (G_DIM * B_DIM);
#pragma unroll 4
    for (int g = 0; g < 64; ++g) {
        xg[obase + (size_t)(g0 + g) * B_DIM + lane] = ebuf[g * 33 + lane] + bias[g0 + g];
    }
}

// ================= tensor-core recurrent kernel (two-phase staging) =================
#define RCTAS 96
#define RTHR  384
#define WPITCH 2312
#define SM_W_BYTES (24 * WPITCH * 2)     // 110976
#define SM_H_OFF   SM_W_BYTES
#define SM_H_BYTES (1536 * 64)           // 98304
#define SM_PART_OFF (SM_H_OFF + SM_H_BYTES)
#define SM_PART_BYTES (12 * 2 * 4 * 32 * 4)
#define SM_BSH_OFF (SM_PART_OFF + SM_PART_BYTES)
#define SM_REC_TOTAL (SM_BSH_OFF + 128)

__device__ __forceinline__ uint32_t hs_chunk(int k, int c) {
    return (uint32_t)((k >> 1) * 8 + ((((k & 1) << 2) | c) ^ ((k >> 1) & 7)));
}

__global__ void __launch_bounds__(RTHR, 1) gru_rec_tc(
    const __nv_bfloat16* __restrict__ WhhB,
    const float* __restrict__ bhh,
    const float* __restrict__ xg,
    const float* __restrict__ res,
    float* __restrict__ out,
    int out_mode)
{
    extern __shared__ __align__(1024) char smr[];
    __nv_bfloat16* Wsm = (__nv_bfloat16*)smr;
    const uint32_t hs_base = (uint32_t)__cvta_generic_to_shared(smr + SM_H_OFF);
    float* part = (float*)(smr + SM_PART_OFF);
    float* bsh  = (float*)(smr + SM_BSH_OFF);

    const int tid = threadIdx.x;
    const int lane = tid & 31;
    const int w = tid >> 5;           // 0..11
    const int kq = w & 3;             // k-quarter (stride-4 pair interleave)
    const int nt = w >> 2;            // gate tile 0..2
    const int cta = blockIdx.x;

    // ---- load W_hh slice into smem ----
#pragma unroll
    for (int i = 0; i < 18; ++i) {
        int task = i * RTHR + tid;
        int n = task / 288, c = task % 288;
        int grow = (n >> 3) * H_DIM + cta * 8 + (n & 7);
        cp16(Wsm + n * WPITCH + c * 8, WhhB + (size_t)grow * KBIG + c * 8);
    }
    if (tid < 24) {
        int gt = tid >> 3, jl = tid & 7;
        bsh[tid] = bhh[gt * H_DIM + cta * 8 + jl];
    }
    if (tid < 256) {
        int jl = tid >> 5, j = cta * 8 + jl;
        g_hs[0][j * B_DIM + lane] = __float2bfloat16(0.f);
        g_hs[0][(768 + j) * B_DIM + lane] = __float2bfloat16(0.f);
    }
    asm volatile("cp.async.commit_group;\n" ::: "memory");
    asm volatile("cp.async.wait_all;\n" ::: "memory");
    __threadfence();
    grid_barrier();

    // ---- per-thread ldsm address components ----
    const int t4 = lane >> 3, r8 = lane & 7;
    const uint32_t w_base = (uint32_t)__cvta_generic_to_shared(Wsm)
                          + (uint32_t)((nt * 8 + r8) * WPITCH * 2 + t4 * 16);
    const int a_roff = ((t4 >> 1) << 3) + r8;
    const int a_c0 = (t4 & 1);

    auto a_addr = [&](int kt, int mt) -> uint32_t {
        int hrow = (kt < 96 ? kt : kt - 96) << 4;
        int krow = hrow + a_roff;
        int c = mt * 2 + a_c0;
        return hs_base + hs_chunk(krow, c) * 16;
    };

    const int jlf = tid >> 5;
    const int jgf = cta * 8 + jlf;
    const int mtF = lane >> 4, m_in = lane & 15;
    const int lane_src = (m_in & 7) * 4 + (jlf >> 1);
    const int regF = (jlf & 1) + 2 * (m_in >> 3);
    float hprev = 0.f;

    for (int t = 0; t < T_STEPS; ++t) {
        // prefetch xg + residual (independent of h)
        float xr = 0.f, xz = 0.f, xn = 0.f, rv = 0.f;
        if (tid < 256) {
            size_t base = (size_t)t * (G_DIM * B_DIM);
            xr = xg[base + (size_t)(0 * H_DIM + jgf) * B_DIM + lane];
            xz = xg[base + (size_t)(1 * H_DIM + jgf) * B_DIM + lane];
            xn = xg[base + (size_t)(2 * H_DIM + jgf) * B_DIM + lane];
            if (res)
                rv = res[(size_t)(T_STEPS - 1 - t) * (H_DIM * B_DIM) +
                         (size_t)jgf * B_DIM + lane];
        }

        // stage h: group0 = hi rows (k<768), group1 = lo rows
        const __nv_bfloat16* hsrc = g_hs[t & 1];
#pragma unroll
        for (int i = 0; i < 8; ++i) {
            int task = i * RTHR + tid;
            int k = task >> 2, c = task & 3;
            cp16a(hs_base + hs_chunk(k, c) * 16, hsrc + k * B_DIM + c * 8);
        }
        asm volatile("cp.async.commit_group;\n" ::: "memory");
#pragma unroll
        for (int i = 8; i < 16; ++i) {
            int task = i * RTHR + tid;
            int k = task >> 2, c = task & 3;
            cp16a(hs_base + hs_chunk(k, c) * 16, hsrc + k * B_DIM + c * 8);
        }
        asm volatile("cp.async.commit_group;\n" ::: "memory");

        float acc0[4] = {0.f, 0.f, 0.f, 0.f};
        float acc1[4] = {0.f, 0.f, 0.f, 0.f};
        auto do_pair = [&](int j) {
            uint32_t b0, b1, b2, b3;
            ldsm_x4a(b0, b1, b2, b3, w_base + (uint32_t)(j * 64));
            uint32_t bA[2] = {b0, b1}, bB[2] = {b2, b3};
            uint32_t a0 = a_addr(2 * j, 0);
            uint32_t a1 = a_addr(2 * j, 1);
            uint32_t af[4];
            ldsm_x4t(af[0], af[1], af[2], af[3], a0);
            mma_bf16(acc0, af, bA);
            ldsm_x4t(af[0], af[1], af[2], af[3], a1);
            mma_bf16(acc1, af, bA);
            ldsm_x4t(af[0], af[1], af[2], af[3], a0 + 1024);
            mma_bf16(acc0, af, bB);
            ldsm_x4t(af[0], af[1], af[2], af[3], a1 + 1024);
            mma_bf16(acc1, af, bB);
        };

        // phase A: pairs touching only hi rows (j<24: hi*Whi ; j>=48: hi*Wlo)
        asm volatile("cp.async.wait_group %0;\n" :: "n"(1) : "memory");
        __syncthreads();
#pragma unroll
        for (int p = 0; p < 6; ++p) do_pair(kq + 4 * p);
#pragma unroll
        for (int p = 0; p < 6; ++p) do_pair(48 + kq + 4 * p);

        // phase B: pairs touching lo rows (j in [24,48): lo*Whi)
        asm volatile("cp.async.wait_group %0;\n" :: "n"(0) : "memory");
        __syncthreads();
#pragma unroll
        for (int p = 0; p < 6; ++p) do_pair(24 + kq + 4 * p);

#pragma unroll
        for (int rg = 0; rg < 4; ++rg) {
            part[((w * 2 + 0) * 4 + rg) * 32 + lane] = acc0[rg];
            part[((w * 2 + 1) * 4 + rg) * 32 + lane] = acc1[rg];
        }
        __syncthreads();

        // ---- finalize: 256 threads = 8 units x 32 batch ----
        if (tid < 256) {
            float g3[3];
#pragma unroll
            for (int gt = 0; gt < 3; ++gt) {
                float s = 0.f;
#pragma unroll
                for (int k4 = 0; k4 < 4; ++k4) {
                    int wsrc = gt * 4 + k4;
                    s += part[((wsrc * 2 + mtF) * 4 + regF) * 32 + lane_src];
                }
                g3[gt] = s + bsh[gt * 8 + jlf];
            }
            float r = 1.f / (1.f + expf(-(xr + g3[0])));
            float z = 1.f / (1.f + expf(-(xz + g3[1])));
            float n = tanhf(xn + r * g3[2]);
            float hv = (1.f - z) * n + z * hprev;
            hprev = hv;
            __nv_bfloat16 hi, lo; split_bf16(hv, hi, lo);
            __nv_bfloat16* hdst = g_hs[(t & 1) ^ 1];
            hdst[jgf * B_DIM + lane] = hi;
            hdst[(768 + jgf) * B_DIM + lane] = lo;
            float ov = rv + hv;
            if (out_mode == 0)
                out[(size_t)t * (H_DIM * B_DIM) + (size_t)jgf * B_DIM + lane] = ov;
            else
                out[((size_t)lane * T_STEPS + (T_STEPS - 1 - t)) * H_DIM + jgf] = ov;
        }
        __threadfence();
        grid_barrier();
    }
}

// ---------------- host launcher ----------------
extern "C" void kernel_launch(void* const* d_in, const int* in_sizes, int n_in,
                              void* d_out, int out_size) {
    const float* x    = (const float*)d_in[0];
    const float* Wih0 = (const float*)d_in[1];
    const float* Whh0 = (const float*)d_in[2];
    const float* bih0 = (const float*)d_in[3];
    const float* bhh0 = (const float*)d_in[4];
    const float* WihS = (const float*)d_in[5];
    const float* WhhS = (const float*)d_in[6];
    const float* bihS = (const float*)d_in[7];
    const float* bhhS = (const float*)d_in[8];
    float* out = (float*)d_out;

    float *xgP, *actA, *actB;
    __nv_bfloat16 *AbigP, *WbigP, *WhhBigP;
    cudaGetSymbolAddress((void**)&xgP, g_xg);
    cudaGetSymbolAddress((void**)&actA, g_actA);
    cudaGetSymbolAddress((void**)&actB, g_actB);
    cudaGetSymbolAddress((void**)&AbigP, g_Abig);
    cudaGetSymbolAddress((void**)&WbigP, g_Wbig);
    cudaGetSymbolAddress((void**)&WhhBigP, g_WhhBig);

    const int GEMM_SMEM = (NSTAGES * STAGE_ELEMS * 2 > 8 * 64 * 33 * 4)
                        ? NSTAGES * STAGE_ELEMS * 2 : 8 * 64 * 33 * 4;
    cudaFuncSetAttribute(gemm_tc, cudaFuncAttributeMaxDynamicSharedMemorySize, GEMM_SMEM);
    cudaFuncSetAttribute(gru_rec_tc, cudaFuncAttributeMaxDynamicSharedMemorySize,
                         (int)SM_REC_TOTAL);

    const int nblk = (G_DIM * H_DIM + 255) / 256;
    auto wih_of = [&](int l) { return (l == 0) ? Wih0 : WihS + (size_t)(l - 1) * G_DIM * H_DIM; };
    auto whh_of = [&](int l) { return (l == 0) ? Whh0 : WhhS + (size_t)(l - 1) * G_DIM * H_DIM; };

    // Launch order chosen so ncu (-s 5 -c 1) captures gru_rec_tc of layer 0:
    // [0] wih0 [1] whh0 [2] wih1 [3] split_x0 [4] gemm0 [5] rec0 ...
    split_w<<<nblk, 256>>>(wih_of(0), WbigP);
    split_w<<<nblk, 256>>>(whh_of(0), WhhBigP);
    split_w<<<nblk, 256>>>(wih_of(1), WbigP + (size_t)1 * G_DIM * KBIG);

    for (int l = 0; l < 4; ++l) {
        const float* bih = (l == 0) ? bih0 : bihS + (size_t)(l - 1) * G_DIM;
        const float* bhh = (l == 0) ? bhh0 : bhhS + (size_t)(l - 1) * G_DIM;

        const float* ain = (l & 1) ? actB : actA;
        float* aout = (l == 3) ? out : ((l & 1) ? actA : actB);

        if (l == 0)
            split_x0<<<T_STEPS, 256>>>(x, AbigP);
        else
            split_act<<<dim3(T_STEPS, H_DIM / 64), 256>>>(ain, AbigP);

        gemm_tc<<<dim3(G_DIM / 128, M_BIG / 128), 256, GEMM_SMEM>>>(
            AbigP, WbigP + (size_t)l * G_DIM * KBIG, bih, xgP);

        gru_rec_tc<<<RCTAS, RTHR, SM_REC_TOTAL>>>(
            WhhBigP + (size_t)l * G_DIM * KBIG, bhh, xgP,
            (l == 0) ? nullptr : ain, aout, (l == 3) ? 1 : 0);

        // deferred weight splits for the NEXT layers (keeps capture alignment)
        if (l == 0) {
            split_w<<<nblk, 256>>>(whh_of(1), WhhBigP + (size_t)1 * G_DIM * KBIG);
            split_w<<<nblk, 256>>>(wih_of(2), WbigP + (size_t)2 * G_DIM * KBIG);
        } else if (l == 1) {
            split_w<<<nblk, 256>>>(whh_of(2), WhhBigP + (size_t)2 * G_DIM * KBIG);
            split_w<<<nblk, 256>>>(wih_of(3), WbigP + (size_t)3 * G_DIM * KBIG);
        } else if (l == 2) {
            split_w<<<nblk, 256>>>(whh_of(3), WhhBigP + (size_t)3 * G_DIM * KBIG);
        }
    }
}

// round 7
// speedup vs baseline: 1.7100x; 1.0451x over previous
#include <cuda_runtime.h>
#include <cuda_bf16.h>
#include <cstdint>

#define T_STEPS 1024
#define H_DIM   768
#define B_DIM   32
#define G_DIM   (3*H_DIM)     // 2304
#define K2      1536          // [hi|lo] packed K for GEMM
#define KBIG    2304          // 3-term K for recurrent W_hh
#define M_BIG   (T_STEPS*B_DIM) // 32768

// ---------------- static device scratch ----------------
__device__ float g_xg[(size_t)T_STEPS * G_DIM * B_DIM];
__device__ float g_actA[(size_t)T_STEPS * H_DIM * B_DIM];
__device__ float g_actB[(size_t)T_STEPS * H_DIM * B_DIM];
__device__ __align__(1024) __nv_bfloat16 g_Abig[(size_t)M_BIG * K2];         // [m][hi|lo]
__device__ __align__(1024) __nv_bfloat16 g_Wbig[(size_t)4 * G_DIM * K2];     // W_ih [g][hi|lo]
__device__ __align__(1024) __nv_bfloat16 g_WhhBig[(size_t)4 * G_DIM * KBIG]; // W_hh 3-term
__device__ __align__(256) __nv_bfloat16 g_hs[2][1536 * B_DIM];  // h split hi/lo, [k][b]
__device__ unsigned int g_arrive = 0;
__device__ volatile unsigned int g_gen = 0;

// ---------------- software grid barrier ----------------
__device__ __forceinline__ void grid_barrier() {
    __syncthreads();
    if (threadIdx.x == 0) {
        unsigned int target = gridDim.x;
        __threadfence();
        unsigned int gen = g_gen;
        if (atomicAdd(&g_arrive, 1) == target - 1) {
            atomicExch(&g_arrive, 0);
            __threadfence();
            g_gen = gen + 1;
        } else {
            while (g_gen == gen) { }
            __threadfence();
        }
    }
    __syncthreads();
}

// ---------------- bf16 two-term split helpers ----------------
__device__ __forceinline__ void split_bf16(float v, __nv_bfloat16& hi, __nv_bfloat16& lo) {
    hi = __float2bfloat16(v);
    lo = __float2bfloat16(v - __bfloat162float(hi));
}

// fast overflow-safe sigmoid / tanh (MUFU-based)
__device__ __forceinline__ float fast_sigmoid(float x) {
    return __fdividef(1.f, 1.f + __expf(-x));
}
__device__ __forceinline__ float fast_tanh(float x) {
    return 2.f * __fdividef(1.f, 1.f + __expf(-2.f * x)) - 1.f;
}

__global__ void __launch_bounds__(256) split_x0(const float* __restrict__ x,
                                                __nv_bfloat16* __restrict__ Ab) {
    int t = blockIdx.x;
    for (int i = threadIdx.x; i < 32 * H_DIM; i += 256) {
        int b = i / H_DIM, d = i % H_DIM;
        float v = x[((size_t)b * T_STEPS + t) * H_DIM + d];
        __nv_bfloat16 hi, lo; split_bf16(v, hi, lo);
        size_t r = ((size_t)t * 32 + b) * K2;
        Ab[r + d] = hi;
        Ab[r + 768 + d] = lo;
    }
}

__global__ void __launch_bounds__(256) split_act(const float* __restrict__ act,
                                                 __nv_bfloat16* __restrict__ Ab) {
    __shared__ float sm[64][33];
    int t = blockIdx.x;
    int d0 = blockIdx.y * 64;
    int ts = T_STEPS - 1 - t;
    for (int i = threadIdx.x; i < 64 * 32; i += 256) {
        int dl = i >> 5, b = i & 31;
        sm[dl][b] = act[((size_t)ts * H_DIM + d0 + dl) * B_DIM + b];
    }
    __syncthreads();
    for (int i = threadIdx.x; i < 32 * 64; i += 256) {
        int b = i >> 6, dl = i & 63;
        float v = sm[dl][b];
        __nv_bfloat16 hi, lo; split_bf16(v, hi, lo);
        size_t r = ((size_t)t * 32 + b) * K2;
        Ab[r + d0 + dl] = hi;
        Ab[r + 768 + d0 + dl] = lo;
    }
}

// W_ih -> [Whi | Wlo] (K=1536)
__global__ void __launch_bounds__(256) split_w2(const float* __restrict__ W,
                                                __nv_bfloat16* __restrict__ Wb) {
    int i = blockIdx.x * 256 + threadIdx.x;
    if (i >= G_DIM * H_DIM) return;
    int g = i / H_DIM, d = i % H_DIM;
    float v = W[i];
    __nv_bfloat16 hi, lo; split_bf16(v, hi, lo);
    size_t r = (size_t)g * K2;
    Wb[r + d] = hi;
    Wb[r + 768 + d] = lo;
}

// W_hh -> [Whi | Whi | Wlo] (K=2304, recurrent layout)
__global__ void __launch_bounds__(256) split_w(const float* __restrict__ W,
                                               __nv_bfloat16* __restrict__ Wb) {
    int i = blockIdx.x * 256 + threadIdx.x;
    if (i >= G_DIM * H_DIM) return;
    int g = i / H_DIM, d = i % H_DIM;
    float v = W[i];
    __nv_bfloat16 hi, lo; split_bf16(v, hi, lo);
    size_t r = (size_t)g * KBIG;
    Wb[r + d] = hi;
    Wb[r + 768 + d] = hi;
    Wb[r + 1536 + d] = lo;
}

// ---------------- common asm helpers ----------------
__device__ __forceinline__ void cp16(void* s, const void* g) {
    uint32_t sa = (uint32_t)__cvta_generic_to_shared(s);
    asm volatile("cp.async.cg.shared.global [%0], [%1], 16;\n" :: "r"(sa), "l"(g));
}
__device__ __forceinline__ void cp16a(uint32_t sa, const void* g) {
    asm volatile("cp.async.cg.shared.global [%0], [%1], 16;\n" :: "r"(sa), "l"(g));
}
__device__ __forceinline__ void ldsm_x4(uint32_t& r0, uint32_t& r1, uint32_t& r2, uint32_t& r3,
                                        const __nv_bfloat16* p) {
    uint32_t a = (uint32_t)__cvta_generic_to_shared(p);
    asm volatile("ldmatrix.sync.aligned.m8n8.x4.shared.b16 {%0,%1,%2,%3}, [%4];\n"
                 : "=r"(r0), "=r"(r1), "=r"(r2), "=r"(r3) : "r"(a));
}
__device__ __forceinline__ void ldsm_x4a(uint32_t& r0, uint32_t& r1, uint32_t& r2, uint32_t& r3,
                                         uint32_t a) {
    asm volatile("ldmatrix.sync.aligned.m8n8.x4.shared.b16 {%0,%1,%2,%3}, [%4];\n"
                 : "=r"(r0), "=r"(r1), "=r"(r2), "=r"(r3) : "r"(a));
}
__device__ __forceinline__ void ldsm_x4t(uint32_t& r0, uint32_t& r1, uint32_t& r2, uint32_t& r3,
                                         uint32_t a) {
    asm volatile("ldmatrix.sync.aligned.m8n8.x4.trans.shared.b16 {%0,%1,%2,%3}, [%4];\n"
                 : "=r"(r0), "=r"(r1), "=r"(r2), "=r"(r3) : "r"(a));
}
__device__ __forceinline__ void mma_bf16(float* c, const uint32_t* a, const uint32_t* b) {
    asm volatile("mma.sync.aligned.m16n8k16.row.col.f32.bf16.bf16.f32 "
                 "{%0,%1,%2,%3}, {%4,%5,%6,%7}, {%8,%9}, {%0,%1,%2,%3};\n"
                 : "+f"(c[0]), "+f"(c[1]), "+f"(c[2]), "+f"(c[3])
                 : "r"(a[0]), "r"(a[1]), "r"(a[2]), "r"(a[3]), "r"(b[0]), "r"(b[1]));
}

// ---------------- input-projection GEMM (K-packed 3-term, 4-stage) ----------------
// Per iter i (k32 over 768): tiles Ahi_i, Alo_i, Whi_i, Wlo_i; 3 mma-sets:
// acc += Ahi*Whi + Alo*Whi + Ahi*Wlo.
#define SPITCH 40
#define T1 (128 * SPITCH)            // elems per tile (128 rows x pitch 40)
#define STG2 (4 * T1)                // 4 tiles per stage
#define GITER 24                     // 768 / 32

__global__ void __launch_bounds__(256, 1) gemm_tc(
    const __nv_bfloat16* __restrict__ A,   // [32768][1536]
    const __nv_bfloat16* __restrict__ Wb,  // [2304][1536]
    const float* __restrict__ bias,
    float* __restrict__ xg)
{
    extern __shared__ char smem_raw[];
    __nv_bfloat16* sm = (__nv_bfloat16*)smem_raw;

    const int tid = threadIdx.x;
    const int lane = tid & 31;
    const int warp = tid >> 5;
    const int wm = warp >> 1;
    const int wn = warp & 1;
    const int gBase = blockIdx.x * 128;
    const int mBase = blockIdx.y * 128;

    float acc[2][8][4];
#pragma unroll
    for (int i = 0; i < 2; ++i)
#pragma unroll
        for (int j = 0; j < 8; ++j)
#pragma unroll
            for (int k = 0; k < 4; ++k) acc[i][j][k] = 0.f;

    // 4 tiles x 128 rows x 4 chunks = 2048 cp16 tasks, 8 per thread
    auto load_tile = [&](int stage, int it) {
        __nv_bfloat16* base = sm + stage * STG2;
        int k0 = it * 32;
        int c = tid & 3;
        int rhalf = tid >> 2;   // 0..63
#pragma unroll
        for (int j = 0; j < 8; ++j) {
            int tile = j >> 1;
            int row = (j & 1) * 64 + rhalf;
            const __nv_bfloat16* src =
                (tile < 2 ? A + (size_t)(mBase + row) * K2
                          : Wb + (size_t)(gBase + row) * K2)
                + (tile & 1) * 768 + k0 + c * 8;
            cp16(base + tile * T1 + row * SPITCH + c * 8, src);
        }
    };

#pragma unroll
    for (int s = 0; s < 3; ++s) {
        load_tile(s, s);
        asm volatile("cp.async.commit_group;\n" ::: "memory");
    }

    for (int it = 0; it < GITER; ++it) {
        asm volatile("cp.async.wait_group %0;\n" :: "n"(2) : "memory");
        __syncthreads();
        int itn = it + 3;
        if (itn < GITER) load_tile(itn & 3, itn);
        asm volatile("cp.async.commit_group;\n" ::: "memory");

        const __nv_bfloat16* Ah = sm + (it & 3) * STG2;
        const __nv_bfloat16* Al = Ah + T1;
        const __nv_bfloat16* Wh = Ah + 2 * T1;
        const __nv_bfloat16* Wl = Ah + 3 * T1;
#pragma unroll
        for (int kk = 0; kk < 2; ++kk) {
            uint32_t afh[2][4], afl[2][4];
            uint32_t bfh[8][2], bfl[8][2];
#pragma unroll
            for (int mt = 0; mt < 2; ++mt) {
                int ro = (wm * 32 + mt * 16 + (lane & 15)) * SPITCH + kk * 16 + (lane >> 4) * 8;
                ldsm_x4(afh[mt][0], afh[mt][1], afh[mt][2], afh[mt][3], Ah + ro);
                ldsm_x4(afl[mt][0], afl[mt][1], afl[mt][2], afl[mt][3], Al + ro);
            }
#pragma unroll
            for (int np = 0; np < 4; ++np) {
                int grp = lane >> 3;
                int ro = (wn * 64 + np * 16 + (grp >> 1) * 8 + (lane & 7)) * SPITCH
                       + kk * 16 + (grp & 1) * 8;
                uint32_t r0, r1, r2, r3;
                ldsm_x4(r0, r1, r2, r3, Wh + ro);
                bfh[2 * np][0] = r0; bfh[2 * np][1] = r1;
                bfh[2 * np + 1][0] = r2; bfh[2 * np + 1][1] = r3;
                ldsm_x4(r0, r1, r2, r3, Wl + ro);
                bfl[2 * np][0] = r0; bfl[2 * np][1] = r1;
                bfl[2 * np + 1][0] = r2; bfl[2 * np + 1][1] = r3;
            }
#pragma unroll
            for (int mt = 0; mt < 2; ++mt)
#pragma unroll
                for (int nt = 0; nt < 8; ++nt) {
                    mma_bf16(acc[mt][nt], afh[mt], bfh[nt]);
                    mma_bf16(acc[mt][nt], afl[mt], bfh[nt]);
                    mma_bf16(acc[mt][nt], afh[mt], bfl[nt]);
                }
        }
    }
    asm volatile("cp.async.wait_all;\n" ::: "memory");
    __syncthreads();

    float* ebuf = (float*)smem_raw + warp * (64 * 33);
#pragma unroll
    for (int mt = 0; mt < 2; ++mt)
#pragma unroll
        for (int nt = 0; nt < 8; ++nt) {
            int b0 = mt * 16 + (lane >> 2);
            int gl = nt * 8 + (lane & 3) * 2;
            ebuf[gl * 33 + b0]            = acc[mt][nt][0];
            ebuf[(gl + 1) * 33 + b0]      = acc[mt][nt][1];
            ebuf[gl * 33 + b0 + 8]        = acc[mt][nt][2];
            ebuf[(gl + 1) * 33 + b0 + 8]  = acc[mt][nt][3];
        }
    __syncwarp();
    int t = blockIdx.y * 4 + wm;
    int g0 = gBase + wn * 64;
    size_t obase = (size_t)t * (G_DIM * B_DIM);
#pragma unroll 4
    for (int g = 0; g < 64; ++g) {
        xg[obase + (size_t)(g0 + g) * B_DIM + lane] = ebuf[g * 33 + lane] + bias[g0 + g];
    }
}
#define GEMM_SMEM ((4 * STG2 * 2 > 8 * 64 * 33 * 4) ? 4 * STG2 * 2 : 8 * 64 * 33 * 4)

// ================= tensor-core recurrent kernel =================
#define RCTAS 96
#define RTHR  384
#define WPITCH 2312
#define SM_W_BYTES (24 * WPITCH * 2)
#define SM_H_OFF   SM_W_BYTES
#define SM_H_BYTES (1536 * 64)
#define SM_PART_OFF (SM_H_OFF + SM_H_BYTES)
#define SM_PART_BYTES (12 * 2 * 4 * 32 * 4)
#define SM_BSH_OFF (SM_PART_OFF + SM_PART_BYTES)
#define SM_REC_TOTAL (SM_BSH_OFF + 128)

__device__ __forceinline__ uint32_t hs_chunk(int k, int c) {
    return (uint32_t)((k >> 1) * 8 + ((((k & 1) << 2) | c) ^ ((k >> 1) & 7)));
}

__global__ void __launch_bounds__(RTHR, 1) gru_rec_tc(
    const __nv_bfloat16* __restrict__ WhhB,
    const float* __restrict__ bhh,
    const float* __restrict__ xg,
    const float* __restrict__ res,
    float* __restrict__ out,
    int out_mode)
{
    extern __shared__ __align__(1024) char smr[];
    __nv_bfloat16* Wsm = (__nv_bfloat16*)smr;
    const uint32_t hs_base = (uint32_t)__cvta_generic_to_shared(smr + SM_H_OFF);
    float* part = (float*)(smr + SM_PART_OFF);
    float* bsh  = (float*)(smr + SM_BSH_OFF);

    const int tid = threadIdx.x;
    const int lane = tid & 31;
    const int w = tid >> 5;
    const int kq = w & 3;
    const int nt = w >> 2;
    const int cta = blockIdx.x;

#pragma unroll
    for (int i = 0; i < 18; ++i) {
        int task = i * RTHR + tid;
        int n = task / 288, c = task % 288;
        int grow = (n >> 3) * H_DIM + cta * 8 + (n & 7);
        cp16(Wsm + n * WPITCH + c * 8, WhhB + (size_t)grow * KBIG + c * 8);
    }
    if (tid < 24) {
        int gt = tid >> 3, jl = tid & 7;
        bsh[tid] = bhh[gt * H_DIM + cta * 8 + jl];
    }
    if (tid < 256) {
        int jl = tid >> 5, j = cta * 8 + jl;
        g_hs[0][j * B_DIM + lane] = __float2bfloat16(0.f);
        g_hs[0][(768 + j) * B_DIM + lane] = __float2bfloat16(0.f);
    }
    asm volatile("cp.async.commit_group;\n" ::: "memory");
    asm volatile("cp.async.wait_all;\n" ::: "memory");
    __threadfence();
    grid_barrier();

    const int t4 = lane >> 3, r8 = lane & 7;
    const uint32_t w_base = (uint32_t)__cvta_generic_to_shared(Wsm)
                          + (uint32_t)((nt * 8 + r8) * WPITCH * 2 + t4 * 16);
    const int a_roff = ((t4 >> 1) << 3) + r8;
    const int a_c0 = (t4 & 1);

    auto a_addr = [&](int kt, int mt) -> uint32_t {
        int hrow = (kt < 96 ? kt : kt - 96) << 4;
        int krow = hrow + a_roff;
        int c = mt * 2 + a_c0;
        return hs_base + hs_chunk(krow, c) * 16;
    };

    const int jlf = tid >> 5;
    const int jgf = cta * 8 + jlf;
    const int mtF = lane >> 4, m_in = lane & 15;
    const int lane_src = (m_in & 7) * 4 + (jlf >> 1);
    const int regF = (jlf & 1) + 2 * (m_in >> 3);
    float hprev = 0.f;

    for (int t = 0; t < T_STEPS; ++t) {
        float xr = 0.f, xz = 0.f, xn = 0.f, rv = 0.f;
        if (tid < 256) {
            size_t base = (size_t)t * (G_DIM * B_DIM);
            xr = xg[base + (size_t)(0 * H_DIM + jgf) * B_DIM + lane];
            xz = xg[base + (size_t)(1 * H_DIM + jgf) * B_DIM + lane];
            xn = xg[base + (size_t)(2 * H_DIM + jgf) * B_DIM + lane];
            if (res)
                rv = res[(size_t)(T_STEPS - 1 - t) * (H_DIM * B_DIM) +
                         (size_t)jgf * B_DIM + lane];
        }

        const __nv_bfloat16* hsrc = g_hs[t & 1];
#pragma unroll
        for (int i = 0; i < 8; ++i) {
            int task = i * RTHR + tid;
            int k = task >> 2, c = task & 3;
            cp16a(hs_base + hs_chunk(k, c) * 16, hsrc + k * B_DIM + c * 8);
        }
        asm volatile("cp.async.commit_group;\n" ::: "memory");
#pragma unroll
        for (int i = 8; i < 16; ++i) {
            int task = i * RTHR + tid;
            int k = task >> 2, c = task & 3;
            cp16a(hs_base + hs_chunk(k, c) * 16, hsrc + k * B_DIM + c * 8);
        }
        asm volatile("cp.async.commit_group;\n" ::: "memory");

        float acc0[4] = {0.f, 0.f, 0.f, 0.f};
        float acc1[4] = {0.f, 0.f, 0.f, 0.f};

        // pair with shared A fragments: W tiles q (Whi) and q+48 (Wlo), hi h rows
        auto do_pairAB = [&](int q) {
            uint32_t a0 = a_addr(2 * q, 0);
            uint32_t a1 = a_addr(2 * q, 1);
            uint32_t fA0[4], fA1[4], fB0[4], fB1[4];
            ldsm_x4t(fA0[0], fA0[1], fA0[2], fA0[3], a0);
            ldsm_x4t(fA1[0], fA1[1], fA1[2], fA1[3], a1);
            ldsm_x4t(fB0[0], fB0[1], fB0[2], fB0[3], a0 + 1024);
            ldsm_x4t(fB1[0], fB1[1], fB1[2], fB1[3], a1 + 1024);
            uint32_t b0, b1, b2, b3;
            ldsm_x4a(b0, b1, b2, b3, w_base + (uint32_t)(q * 64));
            { uint32_t bA[2] = {b0, b1}, bB[2] = {b2, b3};
              mma_bf16(acc0, fA0, bA); mma_bf16(acc1, fA1, bA);
              mma_bf16(acc0, fB0, bB); mma_bf16(acc1, fB1, bB); }
            ldsm_x4a(b0, b1, b2, b3, w_base + (uint32_t)((q + 48) * 64));
            { uint32_t bA[2] = {b0, b1}, bB[2] = {b2, b3};
              mma_bf16(acc0, fA0, bA); mma_bf16(acc1, fA1, bA);
              mma_bf16(acc0, fB0, bB); mma_bf16(acc1, fB1, bB); }
        };
        // lo-row pair (Whi only)
        auto do_pair = [&](int q) {
            uint32_t b0, b1, b2, b3;
            ldsm_x4a(b0, b1, b2, b3, w_base + (uint32_t)(q * 64));
            uint32_t bA[2] = {b0, b1}, bB[2] = {b2, b3};
            uint32_t a0 = a_addr(2 * q, 0);
            uint32_t a1 = a_addr(2 * q, 1);
            uint32_t af[4];
            ldsm_x4t(af[0], af[1], af[2], af[3], a0);
            mma_bf16(acc0, af, bA);
            ldsm_x4t(af[0], af[1], af[2], af[3], a1);
            mma_bf16(acc1, af, bA);
            ldsm_x4t(af[0], af[1], af[2], af[3], a0 + 1024);
            mma_bf16(acc0, af, bB);
            ldsm_x4t(af[0], af[1], af[2], af[3], a1 + 1024);
            mma_bf16(acc1, af, bB);
        };

        // phase A: hi rows (Whi + Wlo terms, shared A frags)
        asm volatile("cp.async.wait_group %0;\n" :: "n"(1) : "memory");
        __syncthreads();
#pragma unroll
        for (int p = 0; p < 6; ++p) do_pairAB(kq + 4 * p);

        // phase B: lo rows (Whi term)
        asm volatile("cp.async.wait_group %0;\n" :: "n"(0) : "memory");
        __syncthreads();
#pragma unroll
        for (int p = 0; p < 6; ++p) do_pair(24 + kq + 4 * p);

#pragma unroll
        for (int rg = 0; rg < 4; ++rg) {
            part[((w * 2 + 0) * 4 + rg) * 32 + lane] = acc0[rg];
            part[((w * 2 + 1) * 4 + rg) * 32 + lane] = acc1[rg];
        }
        __syncthreads();

        if (tid < 256) {
            float g3[3];
#pragma unroll
            for (int gt = 0; gt < 3; ++gt) {
                float s = 0.f;
#pragma unroll
                for (int k4 = 0; k4 < 4; ++k4) {
                    int wsrc = gt * 4 + k4;
                    s += part[((wsrc * 2 + mtF) * 4 + regF) * 32 + lane_src];
                }
                g3[gt] = s + bsh[gt * 8 + jlf];
            }
            float r = fast_sigmoid(xr + g3[0]);
            float z = fast_sigmoid(xz + g3[1]);
            float n = fast_tanh(xn + r * g3[2]);
            float hv = (1.f - z) * n + z * hprev;
            hprev = hv;
            __nv_bfloat16 hi, lo; split_bf16(hv, hi, lo);
            __nv_bfloat16* hdst = g_hs[(t & 1) ^ 1];
            hdst[jgf * B_DIM + lane] = hi;
            hdst[(768 + jgf) * B_DIM + lane] = lo;
            float ov = rv + hv;
            if (out_mode == 0)
                out[(size_t)t * (H_DIM * B_DIM) + (size_t)jgf * B_DIM + lane] = ov;
            else
                out[((size_t)lane * T_STEPS + (T_STEPS - 1 - t)) * H_DIM + jgf] = ov;
            __threadfence();
        }
        grid_barrier();
    }
}

// ---------------- host launcher ----------------
extern "C" void kernel_launch(void* const* d_in, const int* in_sizes, int n_in,
                              void* d_out, int out_size) {
    const float* x    = (const float*)d_in[0];
    const float* Wih0 = (const float*)d_in[1];
    const float* Whh0 = (const float*)d_in[2];
    const float* bih0 = (const float*)d_in[3];
    const float* bhh0 = (const float*)d_in[4];
    const float* WihS = (const float*)d_in[5];
    const float* WhhS = (const float*)d_in[6];
    const float* bihS = (const float*)d_in[7];
    const float* bhhS = (const float*)d_in[8];
    float* out = (float*)d_out;

    float *xgP, *actA, *actB;
    __nv_bfloat16 *AbigP, *WbigP, *WhhBigP;
    cudaGetSymbolAddress((void**)&xgP, g_xg);
    cudaGetSymbolAddress((void**)&actA, g_actA);
    cudaGetSymbolAddress((void**)&actB, g_actB);
    cudaGetSymbolAddress((void**)&AbigP, g_Abig);
    cudaGetSymbolAddress((void**)&WbigP, g_Wbig);
    cudaGetSymbolAddress((void**)&WhhBigP, g_WhhBig);

    cudaFuncSetAttribute(gemm_tc, cudaFuncAttributeMaxDynamicSharedMemorySize,
                         (int)GEMM_SMEM);
    cudaFuncSetAttribute(gru_rec_tc, cudaFuncAttributeMaxDynamicSharedMemorySize,
                         (int)SM_REC_TOTAL);

    const int nblk = (G_DIM * H_DIM + 255) / 256;
    auto wih_of = [&](int l) { return (l == 0) ? Wih0 : WihS + (size_t)(l - 1) * G_DIM * H_DIM; };
    auto whh_of = [&](int l) { return (l == 0) ? Whh0 : WhhS + (size_t)(l - 1) * G_DIM * H_DIM; };

    // ncu alignment: [0] wih0 [1] whh0 [2] wih1 [3] split_x0 [4] gemm0 [5] rec0 ...
    split_w2<<<nblk, 256>>>(wih_of(0), WbigP);
    split_w<<<nblk, 256>>>(whh_of(0), WhhBigP);
    split_w2<<<nblk, 256>>>(wih_of(1), WbigP + (size_t)1 * G_DIM * K2);

    for (int l = 0; l < 4; ++l) {
        const float* bih = (l == 0) ? bih0 : bihS + (size_t)(l - 1) * G_DIM;
        const float* bhh = (l == 0) ? bhh0 : bhhS + (size_t)(l - 1) * G_DIM;

        const float* ain = (l & 1) ? actB : actA;
        float* aout = (l == 3) ? out : ((l & 1) ? actA : actB);

        if (l == 0)
            split_x0<<<T_STEPS, 256>>>(x, AbigP);
        else
            split_act<<<dim3(T_STEPS, H_DIM / 64), 256>>>(ain, AbigP);

        gemm_tc<<<dim3(G_DIM / 128, M_BIG / 128), 256, GEMM_SMEM>>>(
            AbigP, WbigP + (size_t)l * G_DIM * K2, bih, xgP);

        gru_rec_tc<<<RCTAS, RTHR, SM_REC_TOTAL>>>(
            WhhBigP + (size_t)l * G_DIM * KBIG, bhh, xgP,
            (l == 0) ? nullptr : ain, aout, (l == 3) ? 1 : 0);

        if (l == 0) {
            split_w<<<nblk, 256>>>(whh_of(1), WhhBigP + (size_t)1 * G_DIM * KBIG);
            split_w2<<<nblk, 256>>>(wih_of(2), WbigP + (size_t)2 * G_DIM * K2);
        } else if (l == 1) {
            split_w<<<nblk, 256>>>(whh_of(2), WhhBigP + (size_t)2 * G_DIM * KBIG);
            split_w2<<<nblk, 256>>>(wih_of(3), WbigP + (size_t)3 * G_DIM * K2);
        } else if (l == 2) {
            split_w<<<nblk, 256>>>(whh_of(3), WhhBigP + (size_t)3 * G_DIM * KBIG);
        }
    }
}

// round 8
// speedup vs baseline: 1.7911x; 1.0474x over previous
#include <cuda_runtime.h>
#include <cuda_bf16.h>
#include <cstdint>

#define T_STEPS 1024
#define H_DIM   768
#define B_DIM   32
#define G_DIM   (3*H_DIM)     // 2304
#define K2      1536          // [hi|lo] packed K for GEMM
#define KBIG    2304          // 3-term K for recurrent W_hh
#define M_BIG   (T_STEPS*B_DIM) // 32768

// ---------------- static device scratch ----------------
__device__ float g_xg[(size_t)T_STEPS * G_DIM * B_DIM];
__device__ float g_actA[(size_t)T_STEPS * H_DIM * B_DIM];
__device__ float g_actB[(size_t)T_STEPS * H_DIM * B_DIM];
__device__ __align__(1024) __nv_bfloat16 g_Abig[(size_t)M_BIG * K2];
__device__ __align__(1024) __nv_bfloat16 g_Wbig[(size_t)4 * G_DIM * K2];
__device__ __align__(1024) __nv_bfloat16 g_WhhBig[(size_t)4 * G_DIM * KBIG];
__device__ __align__(256) __nv_bfloat16 g_hs[2][1536 * B_DIM];
__device__ unsigned int g_arrive = 0;
__device__ volatile unsigned int g_gen = 0;

// ---------------- bf16 two-term split helpers ----------------
__device__ __forceinline__ void split_bf16(float v, __nv_bfloat16& hi, __nv_bfloat16& lo) {
    hi = __float2bfloat16(v);
    lo = __float2bfloat16(v - __bfloat162float(hi));
}
__device__ __forceinline__ float fast_sigmoid(float x) {
    return __fdividef(1.f, 1.f + __expf(-x));
}
__device__ __forceinline__ float fast_tanh(float x) {
    return 2.f * __fdividef(1.f, 1.f + __expf(-2.f * x)) - 1.f;
}

// ---------------- split kernels ----------------
__global__ void __launch_bounds__(256) split_x0(const float* __restrict__ x,
                                                __nv_bfloat16* __restrict__ Ab) {
    int t = blockIdx.x;
    for (int i = threadIdx.x; i < 32 * H_DIM; i += 256) {
        int b = i / H_DIM, d = i % H_DIM;
        float v = x[((size_t)b * T_STEPS + t) * H_DIM + d];
        __nv_bfloat16 hi, lo; split_bf16(v, hi, lo);
        size_t r = ((size_t)t * 32 + b) * K2;
        Ab[r + d] = hi;
        Ab[r + 768 + d] = lo;
    }
}

__global__ void __launch_bounds__(256) split_act(const float* __restrict__ act,
                                                 __nv_bfloat16* __restrict__ Ab) {
    __shared__ float sm[64][33];
    int t = blockIdx.x;
    int d0 = blockIdx.y * 64;
    int ts = T_STEPS - 1 - t;
    for (int i = threadIdx.x; i < 64 * 32; i += 256) {
        int dl = i >> 5, b = i & 31;
        sm[dl][b] = act[((size_t)ts * H_DIM + d0 + dl) * B_DIM + b];
    }
    __syncthreads();
    for (int i = threadIdx.x; i < 32 * 64; i += 256) {
        int b = i >> 6, dl = i & 63;
        float v = sm[dl][b];
        __nv_bfloat16 hi, lo; split_bf16(v, hi, lo);
        size_t r = ((size_t)t * 32 + b) * K2;
        Ab[r + d0 + dl] = hi;
        Ab[r + 768 + d0 + dl] = lo;
    }
}

__global__ void __launch_bounds__(256) split_w2(const float* __restrict__ W,
                                                __nv_bfloat16* __restrict__ Wb) {
    int i = blockIdx.x * 256 + threadIdx.x;
    if (i >= G_DIM * H_DIM) return;
    int g = i / H_DIM, d = i % H_DIM;
    float v = W[i];
    __nv_bfloat16 hi, lo; split_bf16(v, hi, lo);
    size_t r = (size_t)g * K2;
    Wb[r + d] = hi;
    Wb[r + 768 + d] = lo;
}

__global__ void __launch_bounds__(256) split_w(const float* __restrict__ W,
                                               __nv_bfloat16* __restrict__ Wb) {
    int i = blockIdx.x * 256 + threadIdx.x;
    if (i >= G_DIM * H_DIM) return;
    int g = i / H_DIM, d = i % H_DIM;
    float v = W[i];
    __nv_bfloat16 hi, lo; split_bf16(v, hi, lo);
    size_t r = (size_t)g * KBIG;
    Wb[r + d] = hi;
    Wb[r + 768 + d] = hi;
    Wb[r + 1536 + d] = lo;
}

// fused layer-0 splits (keeps ncu capture slot aligned to gru_rec_tc)
__global__ void __launch_bounds__(256) split_l0(const float* __restrict__ Wih0,
                                                const float* __restrict__ Whh0,
                                                __nv_bfloat16* __restrict__ Wb,
                                                __nv_bfloat16* __restrict__ Whh) {
    int half = gridDim.x >> 1;
    if (blockIdx.x < half) {
        int i = blockIdx.x * 256 + threadIdx.x;
        if (i >= G_DIM * H_DIM) return;
        int g = i / H_DIM, d = i % H_DIM;
        float v = Wih0[i];
        __nv_bfloat16 hi, lo; split_bf16(v, hi, lo);
        size_t r = (size_t)g * K2;
        Wb[r + d] = hi;
        Wb[r + 768 + d] = lo;
    } else {
        int i = (blockIdx.x - half) * 256 + threadIdx.x;
        if (i >= G_DIM * H_DIM) return;
        int g = i / H_DIM, d = i % H_DIM;
        float v = Whh0[i];
        __nv_bfloat16 hi, lo; split_bf16(v, hi, lo);
        size_t r = (size_t)g * KBIG;
        Whh[r + d] = hi;
        Whh[r + 768 + d] = hi;
        Whh[r + 1536 + d] = lo;
    }
}

// ---------------- common asm helpers ----------------
__device__ __forceinline__ void cp16(void* s, const void* g) {
    uint32_t sa = (uint32_t)__cvta_generic_to_shared(s);
    asm volatile("cp.async.cg.shared.global [%0], [%1], 16;\n" :: "r"(sa), "l"(g));
}
__device__ __forceinline__ void cp16a(uint32_t sa, const void* g) {
    asm volatile("cp.async.cg.shared.global [%0], [%1], 16;\n" :: "r"(sa), "l"(g));
}
__device__ __forceinline__ void ldsm_x4(uint32_t& r0, uint32_t& r1, uint32_t& r2, uint32_t& r3,
                                        const __nv_bfloat16* p) {
    uint32_t a = (uint32_t)__cvta_generic_to_shared(p);
    asm volatile("ldmatrix.sync.aligned.m8n8.x4.shared.b16 {%0,%1,%2,%3}, [%4];\n"
                 : "=r"(r0), "=r"(r1), "=r"(r2), "=r"(r3) : "r"(a));
}
__device__ __forceinline__ void ldsm_x4a(uint32_t& r0, uint32_t& r1, uint32_t& r2, uint32_t& r3,
                                         uint32_t a) {
    asm volatile("ldmatrix.sync.aligned.m8n8.x4.shared.b16 {%0,%1,%2,%3}, [%4];\n"
                 : "=r"(r0), "=r"(r1), "=r"(r2), "=r"(r3) : "r"(a));
}
__device__ __forceinline__ void ldsm_x4t(uint32_t& r0, uint32_t& r1, uint32_t& r2, uint32_t& r3,
                                         uint32_t a) {
    asm volatile("ldmatrix.sync.aligned.m8n8.x4.trans.shared.b16 {%0,%1,%2,%3}, [%4];\n"
                 : "=r"(r0), "=r"(r1), "=r"(r2), "=r"(r3) : "r"(a));
}
__device__ __forceinline__ void mma_bf16(float* c, const uint32_t* a, const uint32_t* b) {
    asm volatile("mma.sync.aligned.m16n8k16.row.col.f32.bf16.bf16.f32 "
                 "{%0,%1,%2,%3}, {%4,%5,%6,%7}, {%8,%9}, {%0,%1,%2,%3};\n"
                 : "+f"(c[0]), "+f"(c[1]), "+f"(c[2]), "+f"(c[3])
                 : "r"(a[0]), "r"(a[1]), "r"(a[2]), "r"(a[3]), "r"(b[0]), "r"(b[1]));
}

// ---------------- input-projection GEMM (unchanged from R7) ----------------
#define SPITCH 40
#define T1 (128 * SPITCH)
#define STG2 (4 * T1)
#define GITER 24

__global__ void __launch_bounds__(256, 1) gemm_tc(
    const __nv_bfloat16* __restrict__ A,
    const __nv_bfloat16* __restrict__ Wb,
    const float* __restrict__ bias,
    float* __restrict__ xg)
{
    extern __shared__ char smem_raw[];
    __nv_bfloat16* sm = (__nv_bfloat16*)smem_raw;

    const int tid = threadIdx.x;
    const int lane = tid & 31;
    const int warp = tid >> 5;
    const int wm = warp >> 1;
    const int wn = warp & 1;
    const int gBase = blockIdx.x * 128;
    const int mBase = blockIdx.y * 128;

    float acc[2][8][4];
#pragma unroll
    for (int i = 0; i < 2; ++i)
#pragma unroll
        for (int j = 0; j < 8; ++j)
#pragma unroll
            for (int k = 0; k < 4; ++k) acc[i][j][k] = 0.f;

    auto load_tile = [&](int stage, int it) {
        __nv_bfloat16* base = sm + stage * STG2;
        int k0 = it * 32;
        int c = tid & 3;
        int rhalf = tid >> 2;
#pragma unroll
        for (int j = 0; j < 8; ++j) {
            int tile = j >> 1;
            int row = (j & 1) * 64 + rhalf;
            const __nv_bfloat16* src =
                (tile < 2 ? A + (size_t)(mBase + row) * K2
                          : Wb + (size_t)(gBase + row) * K2)
                + (tile & 1) * 768 + k0 + c * 8;
            cp16(base + tile * T1 + row * SPITCH + c * 8, src);
        }
    };

#pragma unroll
    for (int s = 0; s < 3; ++s) {
        load_tile(s, s);
        asm volatile("cp.async.commit_group;\n" ::: "memory");
    }

    for (int it = 0; it < GITER; ++it) {
        asm volatile("cp.async.wait_group %0;\n" :: "n"(2) : "memory");
        __syncthreads();
        int itn = it + 3;
        if (itn < GITER) load_tile(itn & 3, itn);
        asm volatile("cp.async.commit_group;\n" ::: "memory");

        const __nv_bfloat16* Ah = sm + (it & 3) * STG2;
        const __nv_bfloat16* Al = Ah + T1;
        const __nv_bfloat16* Wh = Ah + 2 * T1;
        const __nv_bfloat16* Wl = Ah + 3 * T1;
#pragma unroll
        for (int kk = 0; kk < 2; ++kk) {
            uint32_t afh[2][4], afl[2][4];
            uint32_t bfh[8][2], bfl[8][2];
#pragma unroll
            for (int mt = 0; mt < 2; ++mt) {
                int ro = (wm * 32 + mt * 16 + (lane & 15)) * SPITCH + kk * 16 + (lane >> 4) * 8;
                ldsm_x4(afh[mt][0], afh[mt][1], afh[mt][2], afh[mt][3], Ah + ro);
                ldsm_x4(afl[mt][0], afl[mt][1], afl[mt][2], afl[mt][3], Al + ro);
            }
#pragma unroll
            for (int np = 0; np < 4; ++np) {
                int grp = lane >> 3;
                int ro = (wn * 64 + np * 16 + (grp >> 1) * 8 + (lane & 7)) * SPITCH
                       + kk * 16 + (grp & 1) * 8;
                uint32_t r0, r1, r2, r3;
                ldsm_x4(r0, r1, r2, r3, Wh + ro);
                bfh[2 * np][0] = r0; bfh[2 * np][1] = r1;
                bfh[2 * np + 1][0] = r2; bfh[2 * np + 1][1] = r3;
                ldsm_x4(r0, r1, r2, r3, Wl + ro);
                bfl[2 * np][0] = r0; bfl[2 * np][1] = r1;
                bfl[2 * np + 1][0] = r2; bfl[2 * np + 1][1] = r3;
            }
#pragma unroll
            for (int mt = 0; mt < 2; ++mt)
#pragma unroll
                for (int nt = 0; nt < 8; ++nt) {
                    mma_bf16(acc[mt][nt], afh[mt], bfh[nt]);
                    mma_bf16(acc[mt][nt], afl[mt], bfh[nt]);
                    mma_bf16(acc[mt][nt], afh[mt], bfl[nt]);
                }
        }
    }
    asm volatile("cp.async.wait_all;\n" ::: "memory");
    __syncthreads();

    float* ebuf = (float*)smem_raw + warp * (64 * 33);
#pragma unroll
    for (int mt = 0; mt < 2; ++mt)
#pragma unroll
        for (int nt = 0; nt < 8; ++nt) {
            int b0 = mt * 16 + (lane >> 2);
            int gl = nt * 8 + (lane & 3) * 2;
            ebuf[gl * 33 + b0]            = acc[mt][nt][0];
            ebuf[(gl + 1) * 33 + b0]      = acc[mt][nt][1];
            ebuf[gl * 33 + b0 + 8]        = acc[mt][nt][2];
            ebuf[(gl + 1) * 33 + b0 + 8]  = acc[mt][nt][3];
        }
    __syncwarp();
    int t = blockIdx.y * 4 + wm;
    int g0 = gBase + wn * 64;
    size_t obase = (size_t)t * (G_DIM * B_DIM);
#pragma unroll 4
    for (int g = 0; g < 64; ++g) {
        xg[obase + (size_t)(g0 + g) * B_DIM + lane] = ebuf[g * 33 + lane] + bias[g0 + g];
    }
}
#define GEMM_SMEM ((4 * STG2 * 2 > 8 * 64 * 33 * 4) ? 4 * STG2 * 2 : 8 * 64 * 33 * 4)

// ================= tensor-core recurrent kernel =================
#define RCTAS 96
#define RTHR  384
#define WPITCH 2312
#define SM_W_BYTES (24 * WPITCH * 2)
#define SM_H_OFF   SM_W_BYTES
#define SM_H_BYTES (1536 * 64)
#define SM_PART_OFF (SM_H_OFF + SM_H_BYTES)
#define SM_PART_BYTES (12 * 2 * 4 * 32 * 4)
#define SM_BSH_OFF (SM_PART_OFF + SM_PART_BYTES)
#define SM_REC_TOTAL (SM_BSH_OFF + 128)

__device__ __forceinline__ uint32_t hs_chunk(int k, int c) {
    return (uint32_t)((k >> 1) * 8 + ((((k & 1) << 2) | c) ^ ((k >> 1) & 7)));
}

__global__ void __launch_bounds__(RTHR, 1) gru_rec_tc(
    const __nv_bfloat16* __restrict__ WhhB,
    const float* __restrict__ bhh,
    const float* __restrict__ xg,
    const float* __restrict__ res,
    float* __restrict__ out,
    int out_mode)
{
    extern __shared__ __align__(1024) char smr[];
    __nv_bfloat16* Wsm = (__nv_bfloat16*)smr;
    const uint32_t hs_base = (uint32_t)__cvta_generic_to_shared(smr + SM_H_OFF);
    float* part = (float*)(smr + SM_PART_OFF);
    float* bsh  = (float*)(smr + SM_BSH_OFF);

    const int tid = threadIdx.x;
    const int lane = tid & 31;
    const int w = tid >> 5;
    const int kq = w & 3;
    const int nt = w >> 2;
    const int cta = blockIdx.x;

#pragma unroll
    for (int i = 0; i < 18; ++i) {
        int task = i * RTHR + tid;
        int n = task / 288, c = task % 288;
        int grow = (n >> 3) * H_DIM + cta * 8 + (n & 7);
        cp16(Wsm + n * WPITCH + c * 8, WhhB + (size_t)grow * KBIG + c * 8);
    }
    if (tid < 24) {
        int gt = tid >> 3, jl = tid & 7;
        bsh[tid] = bhh[gt * H_DIM + cta * 8 + jl];
    }
    if (tid < 256) {
        int jl = tid >> 5, j = cta * 8 + jl;
        g_hs[0][j * B_DIM + lane] = __float2bfloat16(0.f);
        g_hs[0][(768 + j) * B_DIM + lane] = __float2bfloat16(0.f);
    }
    asm volatile("cp.async.commit_group;\n" ::: "memory");
    asm volatile("cp.async.wait_all;\n" ::: "memory");
    __threadfence();

    // initial full barrier
    __syncthreads();
    if (tid == 0) {
        unsigned gen = g_gen;
        if (atomicAdd(&g_arrive, 1) == gridDim.x - 1) {
            atomicExch(&g_arrive, 0);
            __threadfence();
            g_gen = gen + 1;
        }
        while (g_gen == gen) { }
        __threadfence();
    }
    __syncthreads();

    const int t4 = lane >> 3, r8 = lane & 7;
    const uint32_t w_base = (uint32_t)__cvta_generic_to_shared(Wsm)
                          + (uint32_t)((nt * 8 + r8) * WPITCH * 2 + t4 * 16);
    const int a_roff = ((t4 >> 1) << 3) + r8;
    const int a_c0 = (t4 & 1);

    auto a_addr = [&](int kt, int mt) -> uint32_t {
        int hrow = (kt < 96 ? kt : kt - 96) << 4;
        int krow = hrow + a_roff;
        int c = mt * 2 + a_c0;
        return hs_base + hs_chunk(krow, c) * 16;
    };

    const int jlf = tid >> 5;
    const int jgf = cta * 8 + jlf;
    const int mtF = lane >> 4, m_in = lane & 15;
    const int lane_src = (m_in & 7) * 4 + (jlf >> 1);
    const int regF = (jlf & 1) + 2 * (m_in >> 3);
    float hprev = 0.f;

    // prefetch step-0 gate inputs + residual
    float xr = 0.f, xz = 0.f, xn = 0.f, rv = 0.f;
    auto prefetch = [&](int t) {
        if (tid < 256) {
            size_t base = (size_t)t * (G_DIM * B_DIM);
            xr = xg[base + (size_t)(0 * H_DIM + jgf) * B_DIM + lane];
            xz = xg[base + (size_t)(1 * H_DIM + jgf) * B_DIM + lane];
            xn = xg[base + (size_t)(2 * H_DIM + jgf) * B_DIM + lane];
            if (res)
                rv = res[(size_t)(T_STEPS - 1 - t) * (H_DIM * B_DIM) +
                         (size_t)jgf * B_DIM + lane];
        }
    };
    prefetch(0);

    for (int t = 0; t < T_STEPS; ++t) {
        // stage h: group0 = hi rows, group1 = lo rows
        const __nv_bfloat16* hsrc = g_hs[t & 1];
#pragma unroll
        for (int i = 0; i < 8; ++i) {
            int task = i * RTHR + tid;
            int k = task >> 2, c = task & 3;
            cp16a(hs_base + hs_chunk(k, c) * 16, hsrc + k * B_DIM + c * 8);
        }
        asm volatile("cp.async.commit_group;\n" ::: "memory");
#pragma unroll
        for (int i = 8; i < 16; ++i) {
            int task = i * RTHR + tid;
            int k = task >> 2, c = task & 3;
            cp16a(hs_base + hs_chunk(k, c) * 16, hsrc + k * B_DIM + c * 8);
        }
        asm volatile("cp.async.commit_group;\n" ::: "memory");

        float acc0[4] = {0.f, 0.f, 0.f, 0.f};
        float acc1[4] = {0.f, 0.f, 0.f, 0.f};

        auto do_pairAB = [&](int q) {
            uint32_t a0 = a_addr(2 * q, 0);
            uint32_t a1 = a_addr(2 * q, 1);
            uint32_t fA0[4], fA1[4], fB0[4], fB1[4];
            ldsm_x4t(fA0[0], fA0[1], fA0[2], fA0[3], a0);
            ldsm_x4t(fA1[0], fA1[1], fA1[2], fA1[3], a1);
            ldsm_x4t(fB0[0], fB0[1], fB0[2], fB0[3], a0 + 1024);
            ldsm_x4t(fB1[0], fB1[1], fB1[2], fB1[3], a1 + 1024);
            uint32_t b0, b1, b2, b3;
            ldsm_x4a(b0, b1, b2, b3, w_base + (uint32_t)(q * 64));
            { uint32_t bA[2] = {b0, b1}, bB[2] = {b2, b3};
              mma_bf16(acc0, fA0, bA); mma_bf16(acc1, fA1, bA);
              mma_bf16(acc0, fB0, bB); mma_bf16(acc1, fB1, bB); }
            ldsm_x4a(b0, b1, b2, b3, w_base + (uint32_t)((q + 48) * 64));
            { uint32_t bA[2] = {b0, b1}, bB[2] = {b2, b3};
              mma_bf16(acc0, fA0, bA); mma_bf16(acc1, fA1, bA);
              mma_bf16(acc0, fB0, bB); mma_bf16(acc1, fB1, bB); }
        };
        auto do_pair = [&](int q) {
            uint32_t b0, b1, b2, b3;
            ldsm_x4a(b0, b1, b2, b3, w_base + (uint32_t)(q * 64));
            uint32_t bA[2] = {b0, b1}, bB[2] = {b2, b3};
            uint32_t a0 = a_addr(2 * q, 0);
            uint32_t a1 = a_addr(2 * q, 1);
            uint32_t af[4];
            ldsm_x4t(af[0], af[1], af[2], af[3], a0);
            mma_bf16(acc0, af, bA);
            ldsm_x4t(af[0], af[1], af[2], af[3], a1);
            mma_bf16(acc1, af, bA);
            ldsm_x4t(af[0], af[1], af[2], af[3], a0 + 1024);
            mma_bf16(acc0, af, bB);
            ldsm_x4t(af[0], af[1], af[2], af[3], a1 + 1024);
            mma_bf16(acc1, af, bB);
        };

        asm volatile("cp.async.wait_group %0;\n" :: "n"(1) : "memory");
        __syncthreads();
#pragma unroll
        for (int p = 0; p < 6; ++p) do_pairAB(kq + 4 * p);

        asm volatile("cp.async.wait_group %0;\n" :: "n"(0) : "memory");
        __syncthreads();
#pragma unroll
        for (int p = 0; p < 6; ++p) do_pair(24 + kq + 4 * p);

#pragma unroll
        for (int rg = 0; rg < 4; ++rg) {
            part[((w * 2 + 0) * 4 + rg) * 32 + lane] = acc0[rg];
            part[((w * 2 + 1) * 4 + rg) * 32 + lane] = acc1[rg];
        }
        __syncthreads();

        if (tid < 256) {
            float g3[3];
#pragma unroll
            for (int gt = 0; gt < 3; ++gt) {
                float s = 0.f;
#pragma unroll
                for (int k4 = 0; k4 < 4; ++k4) {
                    int wsrc = gt * 4 + k4;
                    s += part[((wsrc * 2 + mtF) * 4 + regF) * 32 + lane_src];
                }
                g3[gt] = s + bsh[gt * 8 + jlf];
            }
            float r = fast_sigmoid(xr + g3[0]);
            float z = fast_sigmoid(xz + g3[1]);
            float n = fast_tanh(xn + r * g3[2]);
            float hv = (1.f - z) * n + z * hprev;
            hprev = hv;
            __nv_bfloat16 hi, lo; split_bf16(hv, hi, lo);
            __nv_bfloat16* hdst = g_hs[(t & 1) ^ 1];
            hdst[jgf * B_DIM + lane] = hi;
            hdst[(768 + jgf) * B_DIM + lane] = lo;
            float ov = rv + hv;
            if (out_mode == 0)
                out[(size_t)t * (H_DIM * B_DIM) + (size_t)jgf * B_DIM + lane] = ov;
            else
                out[((size_t)lane * T_STEPS + (T_STEPS - 1 - t)) * H_DIM + jgf] = ov;
            __threadfence();
        }

        // split barrier: arrive -> prefetch t+1 (hidden in wait window) -> wait
        __syncthreads();
        unsigned gen = 0;
        if (tid == 0) {
            gen = g_gen;
            if (atomicAdd(&g_arrive, 1) == gridDim.x - 1) {
                atomicExch(&g_arrive, 0);
                __threadfence();
                g_gen = gen + 1;
            }
        }
        if (t + 1 < T_STEPS) prefetch(t + 1);
        if (tid == 0) {
            while (g_gen == gen) { }
            __threadfence();
        }
        __syncthreads();
    }
}

// ---------------- host launcher ----------------
extern "C" void kernel_launch(void* const* d_in, const int* in_sizes, int n_in,
                              void* d_out, int out_size) {
    const float* x    = (const float*)d_in[0];
    const float* Wih0 = (const float*)d_in[1];
    const float* Whh0 = (const float*)d_in[2];
    const float* bih0 = (const float*)d_in[3];
    const float* bhh0 = (const float*)d_in[4];
    const float* WihS = (const float*)d_in[5];
    const float* WhhS = (const float*)d_in[6];
    const float* bihS = (const float*)d_in[7];
    const float* bhhS = (const float*)d_in[8];
    float* out = (float*)d_out;

    float *xgP, *actA, *actB;
    __nv_bfloat16 *AbigP, *WbigP, *WhhBigP;
    cudaGetSymbolAddress((void**)&xgP, g_xg);
    cudaGetSymbolAddress((void**)&actA, g_actA);
    cudaGetSymbolAddress((void**)&actB, g_actB);
    cudaGetSymbolAddress((void**)&AbigP, g_Abig);
    cudaGetSymbolAddress((void**)&WbigP, g_Wbig);
    cudaGetSymbolAddress((void**)&WhhBigP, g_WhhBig);

    cudaFuncSetAttribute(gemm_tc, cudaFuncAttributeMaxDynamicSharedMemorySize,
                         (int)GEMM_SMEM);
    cudaFuncSetAttribute(gru_rec_tc, cudaFuncAttributeMaxDynamicSharedMemorySize,
                         (int)SM_REC_TOTAL);

    const int nblk = (G_DIM * H_DIM + 255) / 256;
    auto wih_of = [&](int l) { return (l == 0) ? Wih0 : WihS + (size_t)(l - 1) * G_DIM * H_DIM; };
    auto whh_of = [&](int l) { return (l == 0) ? Whh0 : WhhS + (size_t)(l - 1) * G_DIM * H_DIM; };

    // ncu alignment: [0] split_l0 [1] split_x0 [2] gemm0 [3] rec0 (capture slot)
    split_l0<<<2 * nblk, 256>>>(Wih0, Whh0, WbigP, WhhBigP);

    for (int l = 0; l < 4; ++l) {
        const float* bih = (l == 0) ? bih0 : bihS + (size_t)(l - 1) * G_DIM;
        const float* bhh = (l == 0) ? bhh0 : bhhS + (size_t)(l - 1) * G_DIM;

        const float* ain = (l & 1) ? actB : actA;
        float* aout = (l == 3) ? out : ((l & 1) ? actA : actB);

        if (l == 0)
            split_x0<<<T_STEPS, 256>>>(x, AbigP);
        else
            split_act<<<dim3(T_STEPS, H_DIM / 64), 256>>>(ain, AbigP);

        gemm_tc<<<dim3(G_DIM / 128, M_BIG / 128), 256, GEMM_SMEM>>>(
            AbigP, WbigP + (size_t)l * G_DIM * K2, bih, xgP);

        gru_rec_tc<<<RCTAS, RTHR, SM_REC_TOTAL>>>(
            WhhBigP + (size_t)l * G_DIM * KBIG, bhh, xgP,
            (l == 0) ? nullptr : ain, aout, (l == 3) ? 1 : 0);

        // splits for the NEXT layer after this layer's rec launch
        if (l < 3) {
            split_w2<<<nblk, 256>>>(wih_of(l + 1), WbigP + (size_t)(l + 1) * G_DIM * K2);
            split_w<<<nblk, 256>>>(whh_of(l + 1), WhhBigP + (size_t)(l + 1) * G_DIM * KBIG);
        }
    }
}